// round 5
// baseline (speedup 1.0000x reference)
#include <cuda_runtime.h>
#include <math.h>
#include <stdint.h>

#define DIMC   4096
#define NH     32
#define NKV    8
#define DH     128
#define BB     2
#define TSEQ   2048
#define BT     (BB * TSEQ)
#define KVDIM  (NKV * DH)

__device__ float g_Q[BT * DIMC];
__device__ float g_K[BT * KVDIM];
__device__ float g_V[BT * KVDIM];
__device__ float g_O[BT * DIMC];
__device__ float g_cos[TSEQ * 64];
__device__ float g_sin[TSEQ * 64];

// ---------------- helpers ----------------
__device__ __forceinline__ uint32_t cvt_tf32(float f) {
    uint32_t u;
    asm("cvt.rna.tf32.f32 %0, %1;" : "=r"(u) : "f"(f));
    return u;
}
__device__ __forceinline__ void split_tf32(float x, uint32_t& hi, uint32_t& lo) {
    hi = cvt_tf32(x);
    lo = cvt_tf32(x - __uint_as_float(hi));
}
__device__ __forceinline__ void mma_tf32(float* c, const uint32_t* a, const uint32_t* b) {
    asm volatile(
        "mma.sync.aligned.m16n8k8.row.col.f32.tf32.tf32.f32 "
        "{%0,%1,%2,%3}, {%4,%5,%6,%7}, {%8,%9}, {%0,%1,%2,%3};"
        : "+f"(c[0]), "+f"(c[1]), "+f"(c[2]), "+f"(c[3])
        : "r"(a[0]), "r"(a[1]), "r"(a[2]), "r"(a[3]), "r"(b[0]), "r"(b[1]));
}

// =====================================================================
// TF32 GEMM v2: C[M,N] = A[M,K] @ B[K,N], row-major.
// 128x128 CTA tile, BK=32, 256 threads (8 warps), warp tile 64x32.
// LDG register prefetch -> cvt.tf32 at STS time -> raw-bit LDS fragments.
// Single smem buffer (35.8 KB); two syncs per k-tile.
// =====================================================================
#define GBM 128
#define GBN 128
#define GBK 32
#define ASTR 36
#define BSTR 136
#define GEMM_SMEM_BYTES ((GBM * ASTR + GBK * BSTR) * 4)

__global__ __launch_bounds__(256) void gemm_tf32(const float* __restrict__ A,
                                                 const float* __restrict__ B,
                                                 float* __restrict__ C,
                                                 int M, int N, int K) {
    extern __shared__ float smem[];
    float* As = smem;                     // [128][ASTR]  (tf32 bit patterns)
    float* Bs = smem + GBM * ASTR;        // [32][BSTR]

    const int tid  = threadIdx.x;
    const int brow = blockIdx.y * GBM;
    const int bcol = blockIdx.x * GBN;
    const int wid  = tid >> 5, lane = tid & 31;
    const int g    = lane >> 2, t = lane & 3;
    const int m_base = (wid & 1) * 64;
    const int n_base = (wid >> 1) * 32;

    const int a_r0 = tid >> 3;            // +32*i
    const int a_kc = (tid & 7) * 4;
    const int b_r0 = tid >> 5;            // +8*i
    const int b_nc = (tid & 31) * 4;

    float c[4][4][4];
#pragma unroll
    for (int mi = 0; mi < 4; mi++)
#pragma unroll
        for (int ni = 0; ni < 4; ni++)
#pragma unroll
            for (int r = 0; r < 4; r++) c[mi][ni][r] = 0.f;

    const int KT = K / GBK;

    float4 ra[4], rb[4];
    // prefetch tile 0 into registers
#pragma unroll
    for (int i = 0; i < 4; i++)
        ra[i] = *(const float4*)(A + (long)(brow + a_r0 + 32 * i) * K + a_kc);
#pragma unroll
    for (int i = 0; i < 4; i++)
        rb[i] = *(const float4*)(B + (long)(b_r0 + 8 * i) * N + bcol + b_nc);

    for (int kt = 0; kt < KT; kt++) {
        // store current tile (convert once here)
#pragma unroll
        for (int i = 0; i < 4; i++) {
            float* p = &As[(a_r0 + 32 * i) * ASTR + a_kc];
            *(float4*)p = make_float4(
                __uint_as_float(cvt_tf32(ra[i].x)), __uint_as_float(cvt_tf32(ra[i].y)),
                __uint_as_float(cvt_tf32(ra[i].z)), __uint_as_float(cvt_tf32(ra[i].w)));
        }
#pragma unroll
        for (int i = 0; i < 4; i++) {
            float* p = &Bs[(b_r0 + 8 * i) * BSTR + b_nc];
            *(float4*)p = make_float4(
                __uint_as_float(cvt_tf32(rb[i].x)), __uint_as_float(cvt_tf32(rb[i].y)),
                __uint_as_float(cvt_tf32(rb[i].z)), __uint_as_float(cvt_tf32(rb[i].w)));
        }
        __syncthreads();

        // prefetch next tile (LDG latency overlaps compute below)
        if (kt + 1 < KT) {
            const int k0 = (kt + 1) * GBK;
#pragma unroll
            for (int i = 0; i < 4; i++)
                ra[i] = *(const float4*)(A + (long)(brow + a_r0 + 32 * i) * K + k0 + a_kc);
#pragma unroll
            for (int i = 0; i < 4; i++)
                rb[i] = *(const float4*)(B + (long)(k0 + b_r0 + 8 * i) * N + bcol + b_nc);
        }

        // compute: fragments are pre-converted bit patterns, plain LDS
#pragma unroll
        for (int kk = 0; kk < GBK; kk += 8) {
            uint32_t af[4][4], bf[4][2];
#pragma unroll
            for (int mi = 0; mi < 4; mi++) {
                const float* p = &As[(m_base + 16 * mi + g) * ASTR + kk + t];
                af[mi][0] = __float_as_uint(p[0]);
                af[mi][1] = __float_as_uint(p[8 * ASTR]);
                af[mi][2] = __float_as_uint(p[4]);
                af[mi][3] = __float_as_uint(p[8 * ASTR + 4]);
            }
#pragma unroll
            for (int ni = 0; ni < 4; ni++) {
                const float* p = &Bs[(kk + t) * BSTR + n_base + 8 * ni + g];
                bf[ni][0] = __float_as_uint(p[0]);
                bf[ni][1] = __float_as_uint(p[4 * BSTR]);
            }
#pragma unroll
            for (int mi = 0; mi < 4; mi++)
#pragma unroll
                for (int ni = 0; ni < 4; ni++)
                    mma_tf32(c[mi][ni], af[mi], bf[ni]);
        }
        __syncthreads();
    }

#pragma unroll
    for (int mi = 0; mi < 4; mi++) {
#pragma unroll
        for (int ni = 0; ni < 4; ni++) {
            long row = brow + m_base + 16 * mi + g;
            int  col = bcol + n_base + 8 * ni + 2 * t;
            *(float2*)&C[row * N + col]       = make_float2(c[mi][ni][0], c[mi][ni][1]);
            *(float2*)&C[(row + 8) * N + col] = make_float2(c[mi][ni][2], c[mi][ni][3]);
        }
    }
}

// =====================================================================
// RoPE (unchanged)
// =====================================================================
__global__ void rope_table() {
    int idx = blockIdx.x * 256 + threadIdx.x;
    if (idx >= TSEQ * 64) return;
    int d = idx & 63, t = idx >> 6;
    double inv = pow(10000.0, -(double)d / 64.0);
    double ang = (double)t * inv;
    g_cos[idx] = (float)cos(ang);
    g_sin[idx] = (float)sin(ang);
}

__global__ void rope_apply(float* __restrict__ x, int nheads, int total) {
    int idx = blockIdx.x * 256 + threadIdx.x;
    if (idx >= total) return;
    int d   = idx & 63;
    int bth = idx >> 6;
    int t   = (bth / nheads) % TSEQ;
    long base = (long)bth * 128 + d;
    float c = g_cos[t * 64 + d], s = g_sin[t * 64 + d];
    float x1 = x[base], x2 = x[base + 64];
    x[base]      = x1 * c - x2 * s;
    x[base + 64] = x1 * s + x2 * c;
}

// =====================================================================
// Tensor-core flash attention, 3xTF32 (unchanged from R3)
// =====================================================================
#define FSTR_QK 132
#define FSTR_V  136
#define FSTR_P  68

#define QLO_OFF  0
#define KHI_OFF  (QLO_OFF + 64 * FSTR_QK)
#define KLO_OFF  (KHI_OFF + 64 * FSTR_QK)
#define VHI_OFF  (KLO_OFF + 64 * FSTR_QK)
#define VLO_OFF  (VHI_OFF + 64 * FSTR_V)
#define PHI_OFF  (VLO_OFF + 64 * FSTR_V)
#define PLO_OFF  (PHI_OFF + 64 * FSTR_P)
#define MROW_OFF (PLO_OFF + 64 * FSTR_P)
#define LROW_OFF (MROW_OFF + 64)
#define PMAX_OFF (LROW_OFF + 64)
#define PSUM_OFF (PMAX_OFF + 128)
#define FLASH_TC_FLOATS (PSUM_OFF + 128)
#define FLASH_TC_BYTES  (FLASH_TC_FLOATS * 4)

__global__ __launch_bounds__(256, 1) void flash_tc() {
    extern __shared__ float sm[];
    float* Qlo  = sm + QLO_OFF;
    float* Khi  = sm + KHI_OFF;
    float* Klo  = sm + KLO_OFF;
    float* Vhi  = sm + VHI_OFF;
    float* Vlo  = sm + VLO_OFF;
    float* Phi  = sm + PHI_OFF;
    float* Plo  = sm + PLO_OFF;
    float* mrow = sm + MROW_OFF;
    float* lrow = sm + LROW_OFF;
    float* pmax = sm + PMAX_OFF;
    float* psum = sm + PSUM_OFF;

    const int tid = threadIdx.x;
    const int qt  = blockIdx.x;
    const int bh  = blockIdx.y;
    const int b   = bh >> 5;
    const int h   = bh & 31;
    const int kvh = h >> 2;
    const int q0  = qt * 64;
    const int lane = tid & 31, wid = tid >> 5;
    const int g = lane >> 2, t = lane & 3;
    const int wm = wid & 3, wn = wid >> 2;
    const int r0 = wm * 16 + g;

    const float* Qg = g_Q + ((long)(b * TSEQ + q0)) * DIMC + h * DH;
#pragma unroll
    for (int it = 0; it < 8; it++) {
        int idx = it * 256 + tid;
        int row = idx >> 5, c4 = (idx & 31) << 2;
        *(float4*)&Khi[row * FSTR_QK + c4] = *(const float4*)&Qg[(long)row * DIMC + c4];
    }
    if (tid < 64) { mrow[tid] = -1e30f; lrow[tid] = 0.f; }
    __syncthreads();

    const float scale = 0.0883883476483184f;
    uint32_t qhi[16][4];
    uint32_t qlo[16][4];
#pragma unroll
    for (int kk = 0; kk < 16; kk++) {
        const int c = kk * 8 + t;
        float v0 = Khi[r0 * FSTR_QK + c] * scale;
        float v1 = Khi[(r0 + 8) * FSTR_QK + c] * scale;
        float v2 = Khi[r0 * FSTR_QK + c + 4] * scale;
        float v3 = Khi[(r0 + 8) * FSTR_QK + c + 4] * scale;
        split_tf32(v0, qhi[kk][0], qlo[kk][0]);
        split_tf32(v1, qhi[kk][1], qlo[kk][1]);
        split_tf32(v2, qhi[kk][2], qlo[kk][2]);
        split_tf32(v3, qhi[kk][3], qlo[kk][3]);
    }
    __syncthreads();
    if (wn == 0) {
#pragma unroll
        for (int kk = 0; kk < 16; kk++) {
            const int c = kk * 8 + t;
            Qlo[r0 * FSTR_QK + c]           = __uint_as_float(qlo[kk][0]);
            Qlo[(r0 + 8) * FSTR_QK + c]     = __uint_as_float(qlo[kk][1]);
            Qlo[r0 * FSTR_QK + c + 4]       = __uint_as_float(qlo[kk][2]);
            Qlo[(r0 + 8) * FSTR_QK + c + 4] = __uint_as_float(qlo[kk][3]);
        }
    }

    float oc[8][4];
#pragma unroll
    for (int nt = 0; nt < 8; nt++)
#pragma unroll
        for (int r = 0; r < 4; r++) oc[nt][r] = 0.f;

    for (int kt = 0; kt <= qt; kt++) {
        const int k0 = kt * 64;
        const float* Kg = g_K + ((long)(b * TSEQ + k0)) * KVDIM + kvh * DH;
        const float* Vg = g_V + ((long)(b * TSEQ + k0)) * KVDIM + kvh * DH;

        __syncthreads();
#pragma unroll
        for (int it = 0; it < 8; it++) {
            int idx = it * 256 + tid;
            int row = idx >> 5, c4 = (idx & 31) << 2;
            float4 kq = *(const float4*)&Kg[(long)row * KVDIM + c4];
            float4 vq = *(const float4*)&Vg[(long)row * KVDIM + c4];
            uint32_t h0, h1, h2, h3, l0, l1, l2, l3;
            split_tf32(kq.x, h0, l0); split_tf32(kq.y, h1, l1);
            split_tf32(kq.z, h2, l2); split_tf32(kq.w, h3, l3);
            *(float4*)&Khi[row * FSTR_QK + c4] = make_float4(
                __uint_as_float(h0), __uint_as_float(h1), __uint_as_float(h2), __uint_as_float(h3));
            *(float4*)&Klo[row * FSTR_QK + c4] = make_float4(
                __uint_as_float(l0), __uint_as_float(l1), __uint_as_float(l2), __uint_as_float(l3));
            split_tf32(vq.x, h0, l0); split_tf32(vq.y, h1, l1);
            split_tf32(vq.z, h2, l2); split_tf32(vq.w, h3, l3);
            *(float4*)&Vhi[row * FSTR_V + c4] = make_float4(
                __uint_as_float(h0), __uint_as_float(h1), __uint_as_float(h2), __uint_as_float(h3));
            *(float4*)&Vlo[row * FSTR_V + c4] = make_float4(
                __uint_as_float(l0), __uint_as_float(l1), __uint_as_float(l2), __uint_as_float(l3));
        }
        __syncthreads();

        float sc[4][4];
#pragma unroll
        for (int nt = 0; nt < 4; nt++)
#pragma unroll
            for (int r = 0; r < 4; r++) sc[nt][r] = 0.f;

#pragma unroll
        for (int kk = 0; kk < 16; kk++) {
            const int c = kk * 8 + t;
#pragma unroll
            for (int nt = 0; nt < 4; nt++) {
                const int kr = wn * 32 + nt * 8 + g;
                uint32_t bhf[2], blf[2];
                bhf[0] = __float_as_uint(Khi[kr * FSTR_QK + c]);
                bhf[1] = __float_as_uint(Khi[kr * FSTR_QK + c + 4]);
                blf[0] = __float_as_uint(Klo[kr * FSTR_QK + c]);
                blf[1] = __float_as_uint(Klo[kr * FSTR_QK + c + 4]);
                mma_tf32(sc[nt], qhi[kk], bhf);
                mma_tf32(sc[nt], qlo[kk], bhf);
                mma_tf32(sc[nt], qhi[kk], blf);
            }
        }

        if (kt == qt) {
#pragma unroll
            for (int nt = 0; nt < 4; nt++) {
                int c = wn * 32 + nt * 8 + 2 * t;
                if (c     > r0)     sc[nt][0] = -1e30f;
                if (c + 1 > r0)     sc[nt][1] = -1e30f;
                if (c     > r0 + 8) sc[nt][2] = -1e30f;
                if (c + 1 > r0 + 8) sc[nt][3] = -1e30f;
            }
        }

        float mx0 = -1e30f, mx1 = -1e30f;
#pragma unroll
        for (int nt = 0; nt < 4; nt++) {
            mx0 = fmaxf(mx0, fmaxf(sc[nt][0], sc[nt][1]));
            mx1 = fmaxf(mx1, fmaxf(sc[nt][2], sc[nt][3]));
        }
        mx0 = fmaxf(mx0, __shfl_xor_sync(0xffffffffu, mx0, 1));
        mx0 = fmaxf(mx0, __shfl_xor_sync(0xffffffffu, mx0, 2));
        mx1 = fmaxf(mx1, __shfl_xor_sync(0xffffffffu, mx1, 1));
        mx1 = fmaxf(mx1, __shfl_xor_sync(0xffffffffu, mx1, 2));
        if (t == 0) {
            pmax[wn * 64 + r0]     = mx0;
            pmax[wn * 64 + r0 + 8] = mx1;
        }
        __syncthreads();
        float mold0 = mrow[r0], mold1 = mrow[r0 + 8];
        float mnew0 = fmaxf(mold0, fmaxf(pmax[r0], pmax[64 + r0]));
        float mnew1 = fmaxf(mold1, fmaxf(pmax[r0 + 8], pmax[64 + r0 + 8]));
        float corr0 = __expf(mold0 - mnew0);
        float corr1 = __expf(mold1 - mnew1);

        float sum0 = 0.f, sum1 = 0.f;
#pragma unroll
        for (int nt = 0; nt < 4; nt++) {
            float p00 = __expf(sc[nt][0] - mnew0);
            float p01 = __expf(sc[nt][1] - mnew0);
            float p10 = __expf(sc[nt][2] - mnew1);
            float p11 = __expf(sc[nt][3] - mnew1);
            sum0 += p00 + p01;
            sum1 += p10 + p11;
            uint32_t h00, h01, h10, h11, l00, l01, l10, l11;
            split_tf32(p00, h00, l00); split_tf32(p01, h01, l01);
            split_tf32(p10, h10, l10); split_tf32(p11, h11, l11);
            int c = wn * 32 + nt * 8 + 2 * t;
            *(float2*)&Phi[r0 * FSTR_P + c] =
                make_float2(__uint_as_float(h00), __uint_as_float(h01));
            *(float2*)&Plo[r0 * FSTR_P + c] =
                make_float2(__uint_as_float(l00), __uint_as_float(l01));
            *(float2*)&Phi[(r0 + 8) * FSTR_P + c] =
                make_float2(__uint_as_float(h10), __uint_as_float(h11));
            *(float2*)&Plo[(r0 + 8) * FSTR_P + c] =
                make_float2(__uint_as_float(l10), __uint_as_float(l11));
        }
        sum0 += __shfl_xor_sync(0xffffffffu, sum0, 1);
        sum0 += __shfl_xor_sync(0xffffffffu, sum0, 2);
        sum1 += __shfl_xor_sync(0xffffffffu, sum1, 1);
        sum1 += __shfl_xor_sync(0xffffffffu, sum1, 2);
        if (t == 0) {
            psum[wn * 64 + r0]     = sum0;
            psum[wn * 64 + r0 + 8] = sum1;
        }

#pragma unroll
        for (int nt = 0; nt < 8; nt++) {
            oc[nt][0] *= corr0; oc[nt][1] *= corr0;
            oc[nt][2] *= corr1; oc[nt][3] *= corr1;
        }
        __syncthreads();
        if (wn == 0 && t == 0) {
            mrow[r0] = mnew0;
            mrow[r0 + 8] = mnew1;
            lrow[r0]     = lrow[r0] * corr0 + psum[r0] + psum[64 + r0];
            lrow[r0 + 8] = lrow[r0 + 8] * corr1 + psum[r0 + 8] + psum[64 + r0 + 8];
        }

#pragma unroll
        for (int kk = 0; kk < 8; kk++) {
            const int c = kk * 8 + t;
            uint32_t ph[4], pl[4];
            ph[0] = __float_as_uint(Phi[r0 * FSTR_P + c]);
            ph[1] = __float_as_uint(Phi[(r0 + 8) * FSTR_P + c]);
            ph[2] = __float_as_uint(Phi[r0 * FSTR_P + c + 4]);
            ph[3] = __float_as_uint(Phi[(r0 + 8) * FSTR_P + c + 4]);
            pl[0] = __float_as_uint(Plo[r0 * FSTR_P + c]);
            pl[1] = __float_as_uint(Plo[(r0 + 8) * FSTR_P + c]);
            pl[2] = __float_as_uint(Plo[r0 * FSTR_P + c + 4]);
            pl[3] = __float_as_uint(Plo[(r0 + 8) * FSTR_P + c + 4]);
#pragma unroll
            for (int nt = 0; nt < 8; nt++) {
                const int vc = wn * 64 + nt * 8 + g;
                uint32_t vh[2], vl[2];
                vh[0] = __float_as_uint(Vhi[(kk * 8 + t) * FSTR_V + vc]);
                vh[1] = __float_as_uint(Vhi[(kk * 8 + t + 4) * FSTR_V + vc]);
                vl[0] = __float_as_uint(Vlo[(kk * 8 + t) * FSTR_V + vc]);
                vl[1] = __float_as_uint(Vlo[(kk * 8 + t + 4) * FSTR_V + vc]);
                mma_tf32(oc[nt], ph, vh);
                mma_tf32(oc[nt], pl, vh);
                mma_tf32(oc[nt], ph, vl);
            }
        }
    }

    __syncthreads();
    float linv0 = 1.f / lrow[r0];
    float linv1 = 1.f / lrow[r0 + 8];
    float* Og = g_O + ((long)(b * TSEQ + q0)) * DIMC + h * DH;
#pragma unroll
    for (int nt = 0; nt < 8; nt++) {
        int c = wn * 64 + nt * 8 + 2 * t;
        *(float2*)&Og[(long)r0 * DIMC + c] =
            make_float2(oc[nt][0] * linv0, oc[nt][1] * linv0);
        *(float2*)&Og[(long)(r0 + 8) * DIMC + c] =
            make_float2(oc[nt][2] * linv1, oc[nt][3] * linv1);
    }
}

// =====================================================================
// launch
// =====================================================================
extern "C" void kernel_launch(void* const* d_in, const int* in_sizes, int n_in,
                              void* d_out, int out_size) {
    const float* X  = (const float*)d_in[0];
    const float* Wq = (const float*)d_in[1];
    const float* Wk = (const float*)d_in[2];
    const float* Wv = (const float*)d_in[3];
    const float* Wo = (const float*)d_in[4];
    float* out = (float*)d_out;

    float *Qp, *Kp, *Vp, *Op;
    cudaGetSymbolAddress((void**)&Qp, g_Q);
    cudaGetSymbolAddress((void**)&Kp, g_K);
    cudaGetSymbolAddress((void**)&Vp, g_V);
    cudaGetSymbolAddress((void**)&Op, g_O);

    cudaFuncSetAttribute(gemm_tf32, cudaFuncAttributeMaxDynamicSharedMemorySize,
                         GEMM_SMEM_BYTES);
    cudaFuncSetAttribute(flash_tc, cudaFuncAttributeMaxDynamicSharedMemorySize,
                         FLASH_TC_BYTES);

    rope_table<<<(TSEQ * 64 + 255) / 256, 256>>>();

    gemm_tf32<<<dim3(DIMC / 128, BT / 128), 256, GEMM_SMEM_BYTES>>>(X, Wq, Qp, BT, DIMC, DIMC);
    gemm_tf32<<<dim3(KVDIM / 128, BT / 128), 256, GEMM_SMEM_BYTES>>>(X, Wk, Kp, BT, KVDIM, DIMC);
    gemm_tf32<<<dim3(KVDIM / 128, BT / 128), 256, GEMM_SMEM_BYTES>>>(X, Wv, Vp, BT, KVDIM, DIMC);

    {
        int totq = BT * NH * 64;
        rope_apply<<<(totq + 255) / 256, 256>>>(Qp, NH, totq);
        int totk = BT * NKV * 64;
        rope_apply<<<(totk + 255) / 256, 256>>>(Kp, NKV, totk);
    }

    flash_tc<<<dim3(TSEQ / 64, BB * NH), 256, FLASH_TC_BYTES>>>();

    gemm_tf32<<<dim3(DIMC / 128, BT / 128), 256, GEMM_SMEM_BYTES>>>(Op, Wo, out, BT, DIMC, DIMC);
}

// round 6
// speedup vs baseline: 1.1676x; 1.1676x over previous
#include <cuda_runtime.h>
#include <math.h>
#include <stdint.h>

#define DIMC   4096
#define NH     32
#define NKV    8
#define DH     128
#define BB     2
#define TSEQ   2048
#define BT     (BB * TSEQ)
#define KVDIM  (NKV * DH)

__device__ float g_Q[BT * DIMC];
__device__ float g_K[BT * KVDIM];
__device__ float g_V[BT * KVDIM];
__device__ float g_O[BT * DIMC];        // flash writes tf32-rounded
__device__ float g_cos[TSEQ * 64];
__device__ float g_sin[TSEQ * 64];
// tf32 pre-converted operands
__device__ float g_Xt[BT * DIMC];
__device__ float g_Wqt[DIMC * DIMC];
__device__ float g_Wkt[DIMC * KVDIM];
__device__ float g_Wvt[DIMC * KVDIM];
__device__ float g_Wot[DIMC * DIMC];

// ---------------- helpers ----------------
__device__ __forceinline__ uint32_t cvt_tf32(float f) {
    uint32_t u;
    asm("cvt.rna.tf32.f32 %0, %1;" : "=r"(u) : "f"(f));
    return u;
}
__device__ __forceinline__ void split_tf32(float x, uint32_t& hi, uint32_t& lo) {
    hi = cvt_tf32(x);
    lo = cvt_tf32(x - __uint_as_float(hi));
}
__device__ __forceinline__ void mma_tf32(float* c, const uint32_t* a, const uint32_t* b) {
    asm volatile(
        "mma.sync.aligned.m16n8k8.row.col.f32.tf32.tf32.f32 "
        "{%0,%1,%2,%3}, {%4,%5,%6,%7}, {%8,%9}, {%0,%1,%2,%3};"
        : "+f"(c[0]), "+f"(c[1]), "+f"(c[2]), "+f"(c[3])
        : "r"(a[0]), "r"(a[1]), "r"(a[2]), "r"(a[3]), "r"(b[0]), "r"(b[1]));
}
__device__ __forceinline__ void cpasync16(uint32_t dst, const void* src) {
    asm volatile("cp.async.cg.shared.global [%0], [%1], 16;" :: "r"(dst), "l"(src));
}

// elementwise tf32 pre-conversion (float4 vectorized)
__global__ void cvt_buf(const float* __restrict__ src, float* __restrict__ dst, int n4) {
    int i = blockIdx.x * 256 + threadIdx.x;
    if (i >= n4) return;
    float4 v = ((const float4*)src)[i];
    ((float4*)dst)[i] = make_float4(
        __uint_as_float(cvt_tf32(v.x)), __uint_as_float(cvt_tf32(v.y)),
        __uint_as_float(cvt_tf32(v.z)), __uint_as_float(cvt_tf32(v.w)));
}

// =====================================================================
// TF32 GEMM: operands are PRE-CONVERTED tf32 bit patterns.
// 128x128 CTA tile, BK=32, 256 threads, cp.async double-buffered (as R2/R3).
// Fragment loads are raw LDS (no cvt in the hot loop).
// =====================================================================
#define GBM 128
#define GBN 128
#define GBK 32
#define ASTR 36
#define BSTR 136
#define GEMM_SMEM_BYTES ((2 * GBM * ASTR + 2 * GBK * BSTR) * 4)

__global__ __launch_bounds__(256) void gemm_tf32(const float* __restrict__ A,
                                                 const float* __restrict__ B,
                                                 float* __restrict__ C,
                                                 int M, int N, int K) {
    extern __shared__ float smem[];
    float* As = smem;
    float* Bs = smem + 2 * GBM * ASTR;

    const int tid  = threadIdx.x;
    const int brow = blockIdx.y * GBM;
    const int bcol = blockIdx.x * GBN;
    const int wid  = tid >> 5, lane = tid & 31;
    const int g    = lane >> 2, t = lane & 3;
    const int m_base = (wid & 1) * 64;
    const int n_base = (wid >> 1) * 32;

    const int a_r0 = tid >> 3;
    const int a_kc = (tid & 7) * 4;
    const int b_r0 = tid >> 5;
    const int b_nc = (tid & 31) * 4;

    float c[4][4][4];
#pragma unroll
    for (int mi = 0; mi < 4; mi++)
#pragma unroll
        for (int ni = 0; ni < 4; ni++)
#pragma unroll
            for (int r = 0; r < 4; r++) c[mi][ni][r] = 0.f;

    const int KT = K / GBK;
    {
        float* as = As;
        float* bs = Bs;
#pragma unroll
        for (int i = 0; i < 4; i++) {
            int r = a_r0 + 32 * i;
            cpasync16((uint32_t)__cvta_generic_to_shared(&as[r * ASTR + a_kc]),
                      A + (long)(brow + r) * K + a_kc);
        }
#pragma unroll
        for (int i = 0; i < 4; i++) {
            int r = b_r0 + 8 * i;
            cpasync16((uint32_t)__cvta_generic_to_shared(&bs[r * BSTR + b_nc]),
                      B + (long)r * N + bcol + b_nc);
        }
        asm volatile("cp.async.commit_group;");
    }

    int s = 0;
    for (int kt = 0; kt < KT; kt++) {
        if (kt + 1 < KT) {
            const int k0 = (kt + 1) * GBK;
            float* as = As + (s ^ 1) * GBM * ASTR;
            float* bs = Bs + (s ^ 1) * GBK * BSTR;
#pragma unroll
            for (int i = 0; i < 4; i++) {
                int r = a_r0 + 32 * i;
                cpasync16((uint32_t)__cvta_generic_to_shared(&as[r * ASTR + a_kc]),
                          A + (long)(brow + r) * K + k0 + a_kc);
            }
#pragma unroll
            for (int i = 0; i < 4; i++) {
                int r = b_r0 + 8 * i;
                cpasync16((uint32_t)__cvta_generic_to_shared(&bs[r * BSTR + b_nc]),
                          B + (long)(k0 + r) * N + bcol + b_nc);
            }
            asm volatile("cp.async.commit_group;");
            asm volatile("cp.async.wait_group 1;");
        } else {
            asm volatile("cp.async.wait_group 0;");
        }
        __syncthreads();

        const float* as = As + s * GBM * ASTR;
        const float* bs = Bs + s * GBK * BSTR;
#pragma unroll
        for (int kk = 0; kk < GBK; kk += 8) {
            uint32_t af[4][4], bf[4][2];
#pragma unroll
            for (int mi = 0; mi < 4; mi++) {
                const float* p = &as[(m_base + 16 * mi + g) * ASTR + kk + t];
                af[mi][0] = __float_as_uint(p[0]);
                af[mi][1] = __float_as_uint(p[8 * ASTR]);
                af[mi][2] = __float_as_uint(p[4]);
                af[mi][3] = __float_as_uint(p[8 * ASTR + 4]);
            }
#pragma unroll
            for (int ni = 0; ni < 4; ni++) {
                const float* p = &bs[(kk + t) * BSTR + n_base + 8 * ni + g];
                bf[ni][0] = __float_as_uint(p[0]);
                bf[ni][1] = __float_as_uint(p[4 * BSTR]);
            }
#pragma unroll
            for (int mi = 0; mi < 4; mi++)
#pragma unroll
                for (int ni = 0; ni < 4; ni++)
                    mma_tf32(c[mi][ni], af[mi], bf[ni]);
        }
        __syncthreads();
        s ^= 1;
    }

#pragma unroll
    for (int mi = 0; mi < 4; mi++) {
#pragma unroll
        for (int ni = 0; ni < 4; ni++) {
            long row = brow + m_base + 16 * mi + g;
            int  col = bcol + n_base + 8 * ni + 2 * t;
            *(float2*)&C[row * N + col]       = make_float2(c[mi][ni][0], c[mi][ni][1]);
            *(float2*)&C[(row + 8) * N + col] = make_float2(c[mi][ni][2], c[mi][ni][3]);
        }
    }
}

// =====================================================================
// RoPE (unchanged)
// =====================================================================
__global__ void rope_table() {
    int idx = blockIdx.x * 256 + threadIdx.x;
    if (idx >= TSEQ * 64) return;
    int d = idx & 63, t = idx >> 6;
    double inv = pow(10000.0, -(double)d / 64.0);
    double ang = (double)t * inv;
    g_cos[idx] = (float)cos(ang);
    g_sin[idx] = (float)sin(ang);
}

__global__ void rope_apply(float* __restrict__ x, int nheads, int total) {
    int idx = blockIdx.x * 256 + threadIdx.x;
    if (idx >= total) return;
    int d   = idx & 63;
    int bth = idx >> 6;
    int t   = (bth / nheads) % TSEQ;
    long base = (long)bth * 128 + d;
    float c = g_cos[t * 64 + d], s = g_sin[t * 64 + d];
    float x1 = x[base], x2 = x[base + 64];
    x[base]      = x1 * c - x2 * s;
    x[base + 64] = x1 * s + x2 * c;
}

// =====================================================================
// Tensor-core flash attention, 3xTF32 (R3; epilogue now writes tf32-rounded O)
// =====================================================================
#define FSTR_QK 132
#define FSTR_V  136
#define FSTR_P  68

#define QLO_OFF  0
#define KHI_OFF  (QLO_OFF + 64 * FSTR_QK)
#define KLO_OFF  (KHI_OFF + 64 * FSTR_QK)
#define VHI_OFF  (KLO_OFF + 64 * FSTR_QK)
#define VLO_OFF  (VHI_OFF + 64 * FSTR_V)
#define PHI_OFF  (VLO_OFF + 64 * FSTR_V)
#define PLO_OFF  (PHI_OFF + 64 * FSTR_P)
#define MROW_OFF (PLO_OFF + 64 * FSTR_P)
#define LROW_OFF (MROW_OFF + 64)
#define PMAX_OFF (LROW_OFF + 64)
#define PSUM_OFF (PMAX_OFF + 128)
#define FLASH_TC_FLOATS (PSUM_OFF + 128)
#define FLASH_TC_BYTES  (FLASH_TC_FLOATS * 4)

__global__ __launch_bounds__(256, 1) void flash_tc() {
    extern __shared__ float sm[];
    float* Qlo  = sm + QLO_OFF;
    float* Khi  = sm + KHI_OFF;
    float* Klo  = sm + KLO_OFF;
    float* Vhi  = sm + VHI_OFF;
    float* Vlo  = sm + VLO_OFF;
    float* Phi  = sm + PHI_OFF;
    float* Plo  = sm + PLO_OFF;
    float* mrow = sm + MROW_OFF;
    float* lrow = sm + LROW_OFF;
    float* pmax = sm + PMAX_OFF;
    float* psum = sm + PSUM_OFF;

    const int tid = threadIdx.x;
    const int qt  = blockIdx.x;
    const int bh  = blockIdx.y;
    const int b   = bh >> 5;
    const int h   = bh & 31;
    const int kvh = h >> 2;
    const int q0  = qt * 64;
    const int lane = tid & 31, wid = tid >> 5;
    const int g = lane >> 2, t = lane & 3;
    const int wm = wid & 3, wn = wid >> 2;
    const int r0 = wm * 16 + g;

    const float* Qg = g_Q + ((long)(b * TSEQ + q0)) * DIMC + h * DH;
#pragma unroll
    for (int it = 0; it < 8; it++) {
        int idx = it * 256 + tid;
        int row = idx >> 5, c4 = (idx & 31) << 2;
        *(float4*)&Khi[row * FSTR_QK + c4] = *(const float4*)&Qg[(long)row * DIMC + c4];
    }
    if (tid < 64) { mrow[tid] = -1e30f; lrow[tid] = 0.f; }
    __syncthreads();

    const float scale = 0.0883883476483184f;
    uint32_t qhi[16][4];
    uint32_t qlo[16][4];
#pragma unroll
    for (int kk = 0; kk < 16; kk++) {
        const int c = kk * 8 + t;
        float v0 = Khi[r0 * FSTR_QK + c] * scale;
        float v1 = Khi[(r0 + 8) * FSTR_QK + c] * scale;
        float v2 = Khi[r0 * FSTR_QK + c + 4] * scale;
        float v3 = Khi[(r0 + 8) * FSTR_QK + c + 4] * scale;
        split_tf32(v0, qhi[kk][0], qlo[kk][0]);
        split_tf32(v1, qhi[kk][1], qlo[kk][1]);
        split_tf32(v2, qhi[kk][2], qlo[kk][2]);
        split_tf32(v3, qhi[kk][3], qlo[kk][3]);
    }
    __syncthreads();
    if (wn == 0) {
#pragma unroll
        for (int kk = 0; kk < 16; kk++) {
            const int c = kk * 8 + t;
            Qlo[r0 * FSTR_QK + c]           = __uint_as_float(qlo[kk][0]);
            Qlo[(r0 + 8) * FSTR_QK + c]     = __uint_as_float(qlo[kk][1]);
            Qlo[r0 * FSTR_QK + c + 4]       = __uint_as_float(qlo[kk][2]);
            Qlo[(r0 + 8) * FSTR_QK + c + 4] = __uint_as_float(qlo[kk][3]);
        }
    }

    float oc[8][4];
#pragma unroll
    for (int nt = 0; nt < 8; nt++)
#pragma unroll
        for (int r = 0; r < 4; r++) oc[nt][r] = 0.f;

    for (int kt = 0; kt <= qt; kt++) {
        const int k0 = kt * 64;
        const float* Kg = g_K + ((long)(b * TSEQ + k0)) * KVDIM + kvh * DH;
        const float* Vg = g_V + ((long)(b * TSEQ + k0)) * KVDIM + kvh * DH;

        __syncthreads();
#pragma unroll
        for (int it = 0; it < 8; it++) {
            int idx = it * 256 + tid;
            int row = idx >> 5, c4 = (idx & 31) << 2;
            float4 kq = *(const float4*)&Kg[(long)row * KVDIM + c4];
            float4 vq = *(const float4*)&Vg[(long)row * KVDIM + c4];
            uint32_t h0, h1, h2, h3, l0, l1, l2, l3;
            split_tf32(kq.x, h0, l0); split_tf32(kq.y, h1, l1);
            split_tf32(kq.z, h2, l2); split_tf32(kq.w, h3, l3);
            *(float4*)&Khi[row * FSTR_QK + c4] = make_float4(
                __uint_as_float(h0), __uint_as_float(h1), __uint_as_float(h2), __uint_as_float(h3));
            *(float4*)&Klo[row * FSTR_QK + c4] = make_float4(
                __uint_as_float(l0), __uint_as_float(l1), __uint_as_float(l2), __uint_as_float(l3));
            split_tf32(vq.x, h0, l0); split_tf32(vq.y, h1, l1);
            split_tf32(vq.z, h2, l2); split_tf32(vq.w, h3, l3);
            *(float4*)&Vhi[row * FSTR_V + c4] = make_float4(
                __uint_as_float(h0), __uint_as_float(h1), __uint_as_float(h2), __uint_as_float(h3));
            *(float4*)&Vlo[row * FSTR_V + c4] = make_float4(
                __uint_as_float(l0), __uint_as_float(l1), __uint_as_float(l2), __uint_as_float(l3));
        }
        __syncthreads();

        float sc[4][4];
#pragma unroll
        for (int nt = 0; nt < 4; nt++)
#pragma unroll
            for (int r = 0; r < 4; r++) sc[nt][r] = 0.f;

#pragma unroll
        for (int kk = 0; kk < 16; kk++) {
            const int c = kk * 8 + t;
#pragma unroll
            for (int nt = 0; nt < 4; nt++) {
                const int kr = wn * 32 + nt * 8 + g;
                uint32_t bhf[2], blf[2];
                bhf[0] = __float_as_uint(Khi[kr * FSTR_QK + c]);
                bhf[1] = __float_as_uint(Khi[kr * FSTR_QK + c + 4]);
                blf[0] = __float_as_uint(Klo[kr * FSTR_QK + c]);
                blf[1] = __float_as_uint(Klo[kr * FSTR_QK + c + 4]);
                mma_tf32(sc[nt], qhi[kk], bhf);
                mma_tf32(sc[nt], qlo[kk], bhf);
                mma_tf32(sc[nt], qhi[kk], blf);
            }
        }

        if (kt == qt) {
#pragma unroll
            for (int nt = 0; nt < 4; nt++) {
                int c = wn * 32 + nt * 8 + 2 * t;
                if (c     > r0)     sc[nt][0] = -1e30f;
                if (c + 1 > r0)     sc[nt][1] = -1e30f;
                if (c     > r0 + 8) sc[nt][2] = -1e30f;
                if (c + 1 > r0 + 8) sc[nt][3] = -1e30f;
            }
        }

        float mx0 = -1e30f, mx1 = -1e30f;
#pragma unroll
        for (int nt = 0; nt < 4; nt++) {
            mx0 = fmaxf(mx0, fmaxf(sc[nt][0], sc[nt][1]));
            mx1 = fmaxf(mx1, fmaxf(sc[nt][2], sc[nt][3]));
        }
        mx0 = fmaxf(mx0, __shfl_xor_sync(0xffffffffu, mx0, 1));
        mx0 = fmaxf(mx0, __shfl_xor_sync(0xffffffffu, mx0, 2));
        mx1 = fmaxf(mx1, __shfl_xor_sync(0xffffffffu, mx1, 1));
        mx1 = fmaxf(mx1, __shfl_xor_sync(0xffffffffu, mx1, 2));
        if (t == 0) {
            pmax[wn * 64 + r0]     = mx0;
            pmax[wn * 64 + r0 + 8] = mx1;
        }
        __syncthreads();
        float mold0 = mrow[r0], mold1 = mrow[r0 + 8];
        float mnew0 = fmaxf(mold0, fmaxf(pmax[r0], pmax[64 + r0]));
        float mnew1 = fmaxf(mold1, fmaxf(pmax[r0 + 8], pmax[64 + r0 + 8]));
        float corr0 = __expf(mold0 - mnew0);
        float corr1 = __expf(mold1 - mnew1);

        float sum0 = 0.f, sum1 = 0.f;
#pragma unroll
        for (int nt = 0; nt < 4; nt++) {
            float p00 = __expf(sc[nt][0] - mnew0);
            float p01 = __expf(sc[nt][1] - mnew0);
            float p10 = __expf(sc[nt][2] - mnew1);
            float p11 = __expf(sc[nt][3] - mnew1);
            sum0 += p00 + p01;
            sum1 += p10 + p11;
            uint32_t h00, h01, h10, h11, l00, l01, l10, l11;
            split_tf32(p00, h00, l00); split_tf32(p01, h01, l01);
            split_tf32(p10, h10, l10); split_tf32(p11, h11, l11);
            int c = wn * 32 + nt * 8 + 2 * t;
            *(float2*)&Phi[r0 * FSTR_P + c] =
                make_float2(__uint_as_float(h00), __uint_as_float(h01));
            *(float2*)&Plo[r0 * FSTR_P + c] =
                make_float2(__uint_as_float(l00), __uint_as_float(l01));
            *(float2*)&Phi[(r0 + 8) * FSTR_P + c] =
                make_float2(__uint_as_float(h10), __uint_as_float(h11));
            *(float2*)&Plo[(r0 + 8) * FSTR_P + c] =
                make_float2(__uint_as_float(l10), __uint_as_float(l11));
        }
        sum0 += __shfl_xor_sync(0xffffffffu, sum0, 1);
        sum0 += __shfl_xor_sync(0xffffffffu, sum0, 2);
        sum1 += __shfl_xor_sync(0xffffffffu, sum1, 1);
        sum1 += __shfl_xor_sync(0xffffffffu, sum1, 2);
        if (t == 0) {
            psum[wn * 64 + r0]     = sum0;
            psum[wn * 64 + r0 + 8] = sum1;
        }

#pragma unroll
        for (int nt = 0; nt < 8; nt++) {
            oc[nt][0] *= corr0; oc[nt][1] *= corr0;
            oc[nt][2] *= corr1; oc[nt][3] *= corr1;
        }
        __syncthreads();
        if (wn == 0 && t == 0) {
            mrow[r0] = mnew0;
            mrow[r0 + 8] = mnew1;
            lrow[r0]     = lrow[r0] * corr0 + psum[r0] + psum[64 + r0];
            lrow[r0 + 8] = lrow[r0 + 8] * corr1 + psum[r0 + 8] + psum[64 + r0 + 8];
        }

#pragma unroll
        for (int kk = 0; kk < 8; kk++) {
            const int c = kk * 8 + t;
            uint32_t ph[4], pl[4];
            ph[0] = __float_as_uint(Phi[r0 * FSTR_P + c]);
            ph[1] = __float_as_uint(Phi[(r0 + 8) * FSTR_P + c]);
            ph[2] = __float_as_uint(Phi[r0 * FSTR_P + c + 4]);
            ph[3] = __float_as_uint(Phi[(r0 + 8) * FSTR_P + c + 4]);
            pl[0] = __float_as_uint(Plo[r0 * FSTR_P + c]);
            pl[1] = __float_as_uint(Plo[(r0 + 8) * FSTR_P + c]);
            pl[2] = __float_as_uint(Plo[r0 * FSTR_P + c + 4]);
            pl[3] = __float_as_uint(Plo[(r0 + 8) * FSTR_P + c + 4]);
#pragma unroll
            for (int nt = 0; nt < 8; nt++) {
                const int vc = wn * 64 + nt * 8 + g;
                uint32_t vh[2], vl[2];
                vh[0] = __float_as_uint(Vhi[(kk * 8 + t) * FSTR_V + vc]);
                vh[1] = __float_as_uint(Vhi[(kk * 8 + t + 4) * FSTR_V + vc]);
                vl[0] = __float_as_uint(Vlo[(kk * 8 + t) * FSTR_V + vc]);
                vl[1] = __float_as_uint(Vlo[(kk * 8 + t + 4) * FSTR_V + vc]);
                mma_tf32(oc[nt], ph, vh);
                mma_tf32(oc[nt], pl, vh);
                mma_tf32(oc[nt], ph, vl);
            }
        }
    }

    __syncthreads();
    float linv0 = 1.f / lrow[r0];
    float linv1 = 1.f / lrow[r0 + 8];
    float* Og = g_O + ((long)(b * TSEQ + q0)) * DIMC + h * DH;
#pragma unroll
    for (int nt = 0; nt < 8; nt++) {
        int c = wn * 64 + nt * 8 + 2 * t;
        // write tf32-rounded (identical numerics to cvt at gemm A-frag load)
        *(float2*)&Og[(long)r0 * DIMC + c] = make_float2(
            __uint_as_float(cvt_tf32(oc[nt][0] * linv0)),
            __uint_as_float(cvt_tf32(oc[nt][1] * linv0)));
        *(float2*)&Og[(long)(r0 + 8) * DIMC + c] = make_float2(
            __uint_as_float(cvt_tf32(oc[nt][2] * linv1)),
            __uint_as_float(cvt_tf32(oc[nt][3] * linv1)));
    }
}

// =====================================================================
// launch
// =====================================================================
extern "C" void kernel_launch(void* const* d_in, const int* in_sizes, int n_in,
                              void* d_out, int out_size) {
    const float* X  = (const float*)d_in[0];
    const float* Wq = (const float*)d_in[1];
    const float* Wk = (const float*)d_in[2];
    const float* Wv = (const float*)d_in[3];
    const float* Wo = (const float*)d_in[4];
    float* out = (float*)d_out;

    float *Qp, *Kp, *Vp, *Op, *Xt, *Wqt, *Wkt, *Wvt, *Wot;
    cudaGetSymbolAddress((void**)&Qp, g_Q);
    cudaGetSymbolAddress((void**)&Kp, g_K);
    cudaGetSymbolAddress((void**)&Vp, g_V);
    cudaGetSymbolAddress((void**)&Op, g_O);
    cudaGetSymbolAddress((void**)&Xt, g_Xt);
    cudaGetSymbolAddress((void**)&Wqt, g_Wqt);
    cudaGetSymbolAddress((void**)&Wkt, g_Wkt);
    cudaGetSymbolAddress((void**)&Wvt, g_Wvt);
    cudaGetSymbolAddress((void**)&Wot, g_Wot);

    cudaFuncSetAttribute(gemm_tf32, cudaFuncAttributeMaxDynamicSharedMemorySize,
                         GEMM_SMEM_BYTES);
    cudaFuncSetAttribute(flash_tc, cudaFuncAttributeMaxDynamicSharedMemorySize,
                         FLASH_TC_BYTES);

    rope_table<<<(TSEQ * 64 + 255) / 256, 256>>>();

    // pre-convert operands to tf32 bit patterns (idempotent rounding)
    {
        int n4x = (BT * DIMC) / 4;
        cvt_buf<<<(n4x + 255) / 256, 256>>>(X, Xt, n4x);
        int n4q = (DIMC * DIMC) / 4;
        cvt_buf<<<(n4q + 255) / 256, 256>>>(Wq, Wqt, n4q);
        int n4k = (DIMC * KVDIM) / 4;
        cvt_buf<<<(n4k + 255) / 256, 256>>>(Wk, Wkt, n4k);
        cvt_buf<<<(n4k + 255) / 256, 256>>>(Wv, Wvt, n4k);
        cvt_buf<<<(n4q + 255) / 256, 256>>>(Wo, Wot, n4q);
    }

    gemm_tf32<<<dim3(DIMC / 128, BT / 128), 256, GEMM_SMEM_BYTES>>>(Xt, Wqt, Qp, BT, DIMC, DIMC);
    gemm_tf32<<<dim3(KVDIM / 128, BT / 128), 256, GEMM_SMEM_BYTES>>>(Xt, Wkt, Kp, BT, KVDIM, DIMC);
    gemm_tf32<<<dim3(KVDIM / 128, BT / 128), 256, GEMM_SMEM_BYTES>>>(Xt, Wvt, Vp, BT, KVDIM, DIMC);

    {
        int totq = BT * NH * 64;
        rope_apply<<<(totq + 255) / 256, 256>>>(Qp, NH, totq);
        int totk = BT * NKV * 64;
        rope_apply<<<(totk + 255) / 256, 256>>>(Kp, NKV, totk);
    }

    flash_tc<<<dim3(TSEQ / 64, BB * NH), 256, FLASH_TC_BYTES>>>();

    gemm_tf32<<<dim3(DIMC / 128, BT / 128), 256, GEMM_SMEM_BYTES>>>(Op, Wot, out, BT, DIMC, DIMC);
}

// round 8
// speedup vs baseline: 1.1728x; 1.0045x over previous
#include <cuda_runtime.h>
#include <math.h>
#include <stdint.h>

#define DIMC   4096
#define NH     32
#define NKV    8
#define DH     128
#define BB     2
#define TSEQ   2048
#define BT     (BB * TSEQ)
#define KVDIM  (NKV * DH)

__device__ float g_Q[BT * DIMC];
__device__ float g_K[BT * KVDIM];
__device__ float g_V[BT * KVDIM];
__device__ float g_O[BT * DIMC];        // flash writes tf32-rounded
__device__ float g_cos[TSEQ * 64];
__device__ float g_sin[TSEQ * 64];
// tf32 pre-converted operands
__device__ float g_Xt[BT * DIMC];
__device__ float g_Wqt[DIMC * DIMC];
__device__ float g_Wkt[DIMC * KVDIM];
__device__ float g_Wvt[DIMC * KVDIM];
__device__ float g_Wot[DIMC * DIMC];

// ---------------- helpers ----------------
__device__ __forceinline__ uint32_t cvt_tf32(float f) {
    uint32_t u;
    asm("cvt.rna.tf32.f32 %0, %1;" : "=r"(u) : "f"(f));
    return u;
}
__device__ __forceinline__ void split_tf32(float x, uint32_t& hi, uint32_t& lo) {
    hi = cvt_tf32(x);
    lo = cvt_tf32(x - __uint_as_float(hi));
}
__device__ __forceinline__ void mma_tf32(float* c, const uint32_t* a, const uint32_t* b) {
    asm volatile(
        "mma.sync.aligned.m16n8k8.row.col.f32.tf32.tf32.f32 "
        "{%0,%1,%2,%3}, {%4,%5,%6,%7}, {%8,%9}, {%0,%1,%2,%3};"
        : "+f"(c[0]), "+f"(c[1]), "+f"(c[2]), "+f"(c[3])
        : "r"(a[0]), "r"(a[1]), "r"(a[2]), "r"(a[3]), "r"(b[0]), "r"(b[1]));
}
__device__ __forceinline__ void cpasync16(uint32_t dst, const void* src) {
    asm volatile("cp.async.cg.shared.global [%0], [%1], 16;" :: "r"(dst), "l"(src));
}
// ldmatrix x4 on 32-bit elements (b16 pairs = whole tf32 values)
__device__ __forceinline__ void ldsm_x4(uint32_t* r, uint32_t addr) {
    asm volatile("ldmatrix.sync.aligned.m8n8.x4.shared.b16 {%0,%1,%2,%3}, [%4];"
                 : "=r"(r[0]), "=r"(r[1]), "=r"(r[2]), "=r"(r[3]) : "r"(addr));
}

// elementwise tf32 pre-conversion (float4 vectorized)
__global__ void cvt_buf(const float* __restrict__ src, float* __restrict__ dst, int n4) {
    int i = blockIdx.x * 256 + threadIdx.x;
    if (i >= n4) return;
    float4 v = ((const float4*)src)[i];
    ((float4*)dst)[i] = make_float4(
        __uint_as_float(cvt_tf32(v.x)), __uint_as_float(cvt_tf32(v.y)),
        __uint_as_float(cvt_tf32(v.z)), __uint_as_float(cvt_tf32(v.w)));
}

// =====================================================================
// TF32 GEMM: pre-converted operands, cp.async double-buffered,
// A-fragments via ldmatrix.x4 (ordering matches m16n8k8 A frag).
// =====================================================================
#define GBM 128
#define GBN 128
#define GBK 32
#define ASTR 36
#define BSTR 136
#define GEMM_SMEM_BYTES ((2 * GBM * ASTR + 2 * GBK * BSTR) * 4)

__global__ __launch_bounds__(256) void gemm_tf32(const float* __restrict__ A,
                                                 const float* __restrict__ B,
                                                 float* __restrict__ C,
                                                 int M, int N, int K) {
    extern __shared__ float smem[];
    float* As = smem;
    float* Bs = smem + 2 * GBM * ASTR;

    const int tid  = threadIdx.x;
    const int brow = blockIdx.y * GBM;
    const int bcol = blockIdx.x * GBN;
    const int wid  = tid >> 5, lane = tid & 31;
    const int g    = lane >> 2, t = lane & 3;
    const int m_base = (wid & 1) * 64;
    const int n_base = (wid >> 1) * 32;

    const int a_r0 = tid >> 3;
    const int a_kc = (tid & 7) * 4;
    const int b_r0 = tid >> 5;
    const int b_nc = (tid & 31) * 4;

    // ldmatrix lane -> row/col-half mapping
    const int xr = lane & 15;
    const int xc = (lane >> 4) << 2;
    const uint32_t sA = (uint32_t)__cvta_generic_to_shared(As);
    uint32_t aoff[4];
#pragma unroll
    for (int mi = 0; mi < 4; mi++)
        aoff[mi] = ((m_base + 16 * mi + xr) * ASTR + xc) * 4;

    float c[4][4][4];
#pragma unroll
    for (int mi = 0; mi < 4; mi++)
#pragma unroll
        for (int ni = 0; ni < 4; ni++)
#pragma unroll
            for (int r = 0; r < 4; r++) c[mi][ni][r] = 0.f;

    const int KT = K / GBK;
    {
        float* as = As;
        float* bs = Bs;
#pragma unroll
        for (int i = 0; i < 4; i++) {
            int r = a_r0 + 32 * i;
            cpasync16((uint32_t)__cvta_generic_to_shared(&as[r * ASTR + a_kc]),
                      A + (long)(brow + r) * K + a_kc);
        }
#pragma unroll
        for (int i = 0; i < 4; i++) {
            int r = b_r0 + 8 * i;
            cpasync16((uint32_t)__cvta_generic_to_shared(&bs[r * BSTR + b_nc]),
                      B + (long)r * N + bcol + b_nc);
        }
        asm volatile("cp.async.commit_group;");
    }

    int s = 0;
    for (int kt = 0; kt < KT; kt++) {
        if (kt + 1 < KT) {
            const int k0 = (kt + 1) * GBK;
            float* as = As + (s ^ 1) * GBM * ASTR;
            float* bs = Bs + (s ^ 1) * GBK * BSTR;
#pragma unroll
            for (int i = 0; i < 4; i++) {
                int r = a_r0 + 32 * i;
                cpasync16((uint32_t)__cvta_generic_to_shared(&as[r * ASTR + a_kc]),
                          A + (long)(brow + r) * K + k0 + a_kc);
            }
#pragma unroll
            for (int i = 0; i < 4; i++) {
                int r = b_r0 + 8 * i;
                cpasync16((uint32_t)__cvta_generic_to_shared(&bs[r * BSTR + b_nc]),
                          B + (long)(k0 + r) * N + bcol + b_nc);
            }
            asm volatile("cp.async.commit_group;");
            asm volatile("cp.async.wait_group 1;");
        } else {
            asm volatile("cp.async.wait_group 0;");
        }
        __syncthreads();

        const uint32_t abase = sA + (uint32_t)(s * GBM * ASTR * 4);
        const float* bs = Bs + s * GBK * BSTR;
#pragma unroll
        for (int kk = 0; kk < GBK; kk += 8) {
            uint32_t af[4][4], bf[4][2];
#pragma unroll
            for (int mi = 0; mi < 4; mi++)
                ldsm_x4(af[mi], abase + aoff[mi] + kk * 4);
#pragma unroll
            for (int ni = 0; ni < 4; ni++) {
                const float* p = &bs[(kk + t) * BSTR + n_base + 8 * ni + g];
                bf[ni][0] = __float_as_uint(p[0]);
                bf[ni][1] = __float_as_uint(p[4 * BSTR]);
            }
#pragma unroll
            for (int mi = 0; mi < 4; mi++)
#pragma unroll
                for (int ni = 0; ni < 4; ni++)
                    mma_tf32(c[mi][ni], af[mi], bf[ni]);
        }
        __syncthreads();
        s ^= 1;
    }

#pragma unroll
    for (int mi = 0; mi < 4; mi++) {
#pragma unroll
        for (int ni = 0; ni < 4; ni++) {
            long row = brow + m_base + 16 * mi + g;
            int  col = bcol + n_base + 8 * ni + 2 * t;
            *(float2*)&C[row * N + col]       = make_float2(c[mi][ni][0], c[mi][ni][1]);
            *(float2*)&C[(row + 8) * N + col] = make_float2(c[mi][ni][2], c[mi][ni][3]);
        }
    }
}

// =====================================================================
// RoPE (unchanged)
// =====================================================================
__global__ void rope_table() {
    int idx = blockIdx.x * 256 + threadIdx.x;
    if (idx >= TSEQ * 64) return;
    int d = idx & 63, t = idx >> 6;
    double inv = pow(10000.0, -(double)d / 64.0);
    double ang = (double)t * inv;
    g_cos[idx] = (float)cos(ang);
    g_sin[idx] = (float)sin(ang);
}

__global__ void rope_apply(float* __restrict__ x, int nheads, int total) {
    int idx = blockIdx.x * 256 + threadIdx.x;
    if (idx >= total) return;
    int d   = idx & 63;
    int bth = idx >> 6;
    int t   = (bth / nheads) % TSEQ;
    long base = (long)bth * 128 + d;
    float c = g_cos[t * 64 + d], s = g_sin[t * 64 + d];
    float x1 = x[base], x2 = x[base + 64];
    x[base]      = x1 * c - x2 * s;
    x[base + 64] = x1 * s + x2 * c;
}

// =====================================================================
// Tensor-core flash attention, 3xTF32. K/P fragments via ldmatrix.
// =====================================================================
#define FSTR_QK 132
#define FSTR_V  136
#define FSTR_P  68

#define QLO_OFF  0
#define KHI_OFF  (QLO_OFF + 64 * FSTR_QK)
#define KLO_OFF  (KHI_OFF + 64 * FSTR_QK)
#define VHI_OFF  (KLO_OFF + 64 * FSTR_QK)
#define VLO_OFF  (VHI_OFF + 64 * FSTR_V)
#define PHI_OFF  (VLO_OFF + 64 * FSTR_V)
#define PLO_OFF  (PHI_OFF + 64 * FSTR_P)
#define MROW_OFF (PLO_OFF + 64 * FSTR_P)
#define LROW_OFF (MROW_OFF + 64)
#define PMAX_OFF (LROW_OFF + 64)
#define PSUM_OFF (PMAX_OFF + 128)
#define FLASH_TC_FLOATS (PSUM_OFF + 128)
#define FLASH_TC_BYTES  (FLASH_TC_FLOATS * 4)

__global__ __launch_bounds__(256, 1) void flash_tc() {
    extern __shared__ float sm[];
    float* Qlo  = sm + QLO_OFF;
    float* Khi  = sm + KHI_OFF;
    float* Klo  = sm + KLO_OFF;
    float* Vhi  = sm + VHI_OFF;
    float* Vlo  = sm + VLO_OFF;
    float* Phi  = sm + PHI_OFF;
    float* Plo  = sm + PLO_OFF;
    float* mrow = sm + MROW_OFF;
    float* lrow = sm + LROW_OFF;
    float* pmax = sm + PMAX_OFF;
    float* psum = sm + PSUM_OFF;

    const int tid = threadIdx.x;
    const int qt  = blockIdx.x;
    const int bh  = blockIdx.y;
    const int b   = bh >> 5;
    const int h   = bh & 31;
    const int kvh = h >> 2;
    const int q0  = qt * 64;
    const int lane = tid & 31, wid = tid >> 5;
    const int g = lane >> 2, t = lane & 3;
    const int wm = wid & 3, wn = wid >> 2;
    const int r0 = wm * 16 + g;

    // ldmatrix lane -> row/col-half mapping (xr/xc; distinct from lrow array)
    const int xr = lane & 15;
    const int xc = (lane >> 4) << 2;
    const uint32_t smb = (uint32_t)__cvta_generic_to_shared(sm);
    uint32_t khoff[2], kloff[2];
#pragma unroll
    for (int j = 0; j < 2; j++) {
        khoff[j] = (KHI_OFF + (wn * 32 + 16 * j + xr) * FSTR_QK + xc) * 4;
        kloff[j] = (KLO_OFF + (wn * 32 + 16 * j + xr) * FSTR_QK + xc) * 4;
    }
    const uint32_t phoff = (PHI_OFF + (wm * 16 + xr) * FSTR_P + xc) * 4;
    const uint32_t ploff = (PLO_OFF + (wm * 16 + xr) * FSTR_P + xc) * 4;

    const float* Qg = g_Q + ((long)(b * TSEQ + q0)) * DIMC + h * DH;
#pragma unroll
    for (int it = 0; it < 8; it++) {
        int idx = it * 256 + tid;
        int row = idx >> 5, c4 = (idx & 31) << 2;
        *(float4*)&Khi[row * FSTR_QK + c4] = *(const float4*)&Qg[(long)row * DIMC + c4];
    }
    if (tid < 64) { mrow[tid] = -1e30f; lrow[tid] = 0.f; }
    __syncthreads();

    const float scale = 0.0883883476483184f;
    uint32_t qhi[16][4];
    uint32_t qlo[16][4];
#pragma unroll
    for (int kk = 0; kk < 16; kk++) {
        const int c = kk * 8 + t;
        float v0 = Khi[r0 * FSTR_QK + c] * scale;
        float v1 = Khi[(r0 + 8) * FSTR_QK + c] * scale;
        float v2 = Khi[r0 * FSTR_QK + c + 4] * scale;
        float v3 = Khi[(r0 + 8) * FSTR_QK + c + 4] * scale;
        split_tf32(v0, qhi[kk][0], qlo[kk][0]);
        split_tf32(v1, qhi[kk][1], qlo[kk][1]);
        split_tf32(v2, qhi[kk][2], qlo[kk][2]);
        split_tf32(v3, qhi[kk][3], qlo[kk][3]);
    }
    __syncthreads();
    if (wn == 0) {
#pragma unroll
        for (int kk = 0; kk < 16; kk++) {
            const int c = kk * 8 + t;
            Qlo[r0 * FSTR_QK + c]           = __uint_as_float(qlo[kk][0]);
            Qlo[(r0 + 8) * FSTR_QK + c]     = __uint_as_float(qlo[kk][1]);
            Qlo[r0 * FSTR_QK + c + 4]       = __uint_as_float(qlo[kk][2]);
            Qlo[(r0 + 8) * FSTR_QK + c + 4] = __uint_as_float(qlo[kk][3]);
        }
    }

    float oc[8][4];
#pragma unroll
    for (int nt = 0; nt < 8; nt++)
#pragma unroll
        for (int r = 0; r < 4; r++) oc[nt][r] = 0.f;

    for (int kt = 0; kt <= qt; kt++) {
        const int k0 = kt * 64;
        const float* Kg = g_K + ((long)(b * TSEQ + k0)) * KVDIM + kvh * DH;
        const float* Vg = g_V + ((long)(b * TSEQ + k0)) * KVDIM + kvh * DH;

        __syncthreads();
#pragma unroll
        for (int it = 0; it < 8; it++) {
            int idx = it * 256 + tid;
            int row = idx >> 5, c4 = (idx & 31) << 2;
            float4 kq = *(const float4*)&Kg[(long)row * KVDIM + c4];
            float4 vq = *(const float4*)&Vg[(long)row * KVDIM + c4];
            uint32_t h0, h1, h2, h3, l0, l1, l2, l3;
            split_tf32(kq.x, h0, l0); split_tf32(kq.y, h1, l1);
            split_tf32(kq.z, h2, l2); split_tf32(kq.w, h3, l3);
            *(float4*)&Khi[row * FSTR_QK + c4] = make_float4(
                __uint_as_float(h0), __uint_as_float(h1), __uint_as_float(h2), __uint_as_float(h3));
            *(float4*)&Klo[row * FSTR_QK + c4] = make_float4(
                __uint_as_float(l0), __uint_as_float(l1), __uint_as_float(l2), __uint_as_float(l3));
            split_tf32(vq.x, h0, l0); split_tf32(vq.y, h1, l1);
            split_tf32(vq.z, h2, l2); split_tf32(vq.w, h3, l3);
            *(float4*)&Vhi[row * FSTR_V + c4] = make_float4(
                __uint_as_float(h0), __uint_as_float(h1), __uint_as_float(h2), __uint_as_float(h3));
            *(float4*)&Vlo[row * FSTR_V + c4] = make_float4(
                __uint_as_float(l0), __uint_as_float(l1), __uint_as_float(l2), __uint_as_float(l3));
        }
        __syncthreads();

        float sc[4][4];
#pragma unroll
        for (int nt = 0; nt < 4; nt++)
#pragma unroll
            for (int r = 0; r < 4; r++) sc[nt][r] = 0.f;

#pragma unroll
        for (int kk = 0; kk < 16; kk++) {
            uint32_t bh4[2][4], bl4[2][4];
#pragma unroll
            for (int j = 0; j < 2; j++) {
                ldsm_x4(bh4[j], smb + khoff[j] + kk * 32);
                ldsm_x4(bl4[j], smb + kloff[j] + kk * 32);
            }
#pragma unroll
            for (int j = 0; j < 2; j++) {
#pragma unroll
                for (int hh = 0; hh < 2; hh++) {
                    const int nt = 2 * j + hh;
                    uint32_t bhf[2] = { bh4[j][hh], bh4[j][2 + hh] };
                    uint32_t blf[2] = { bl4[j][hh], bl4[j][2 + hh] };
                    mma_tf32(sc[nt], qhi[kk], bhf);
                    mma_tf32(sc[nt], qlo[kk], bhf);
                    mma_tf32(sc[nt], qhi[kk], blf);
                }
            }
        }

        if (kt == qt) {
#pragma unroll
            for (int nt = 0; nt < 4; nt++) {
                int c = wn * 32 + nt * 8 + 2 * t;
                if (c     > r0)     sc[nt][0] = -1e30f;
                if (c + 1 > r0)     sc[nt][1] = -1e30f;
                if (c     > r0 + 8) sc[nt][2] = -1e30f;
                if (c + 1 > r0 + 8) sc[nt][3] = -1e30f;
            }
        }

        float mx0 = -1e30f, mx1 = -1e30f;
#pragma unroll
        for (int nt = 0; nt < 4; nt++) {
            mx0 = fmaxf(mx0, fmaxf(sc[nt][0], sc[nt][1]));
            mx1 = fmaxf(mx1, fmaxf(sc[nt][2], sc[nt][3]));
        }
        mx0 = fmaxf(mx0, __shfl_xor_sync(0xffffffffu, mx0, 1));
        mx0 = fmaxf(mx0, __shfl_xor_sync(0xffffffffu, mx0, 2));
        mx1 = fmaxf(mx1, __shfl_xor_sync(0xffffffffu, mx1, 1));
        mx1 = fmaxf(mx1, __shfl_xor_sync(0xffffffffu, mx1, 2));
        if (t == 0) {
            pmax[wn * 64 + r0]     = mx0;
            pmax[wn * 64 + r0 + 8] = mx1;
        }
        __syncthreads();
        float mold0 = mrow[r0], mold1 = mrow[r0 + 8];
        float mnew0 = fmaxf(mold0, fmaxf(pmax[r0], pmax[64 + r0]));
        float mnew1 = fmaxf(mold1, fmaxf(pmax[r0 + 8], pmax[64 + r0 + 8]));
        float corr0 = __expf(mold0 - mnew0);
        float corr1 = __expf(mold1 - mnew1);

        float sum0 = 0.f, sum1 = 0.f;
#pragma unroll
        for (int nt = 0; nt < 4; nt++) {
            float p00 = __expf(sc[nt][0] - mnew0);
            float p01 = __expf(sc[nt][1] - mnew0);
            float p10 = __expf(sc[nt][2] - mnew1);
            float p11 = __expf(sc[nt][3] - mnew1);
            sum0 += p00 + p01;
            sum1 += p10 + p11;
            uint32_t h00, h01, h10, h11, l00, l01, l10, l11;
            split_tf32(p00, h00, l00); split_tf32(p01, h01, l01);
            split_tf32(p10, h10, l10); split_tf32(p11, h11, l11);
            int c = wn * 32 + nt * 8 + 2 * t;
            *(float2*)&Phi[r0 * FSTR_P + c] =
                make_float2(__uint_as_float(h00), __uint_as_float(h01));
            *(float2*)&Plo[r0 * FSTR_P + c] =
                make_float2(__uint_as_float(l00), __uint_as_float(l01));
            *(float2*)&Phi[(r0 + 8) * FSTR_P + c] =
                make_float2(__uint_as_float(h10), __uint_as_float(h11));
            *(float2*)&Plo[(r0 + 8) * FSTR_P + c] =
                make_float2(__uint_as_float(l10), __uint_as_float(l11));
        }
        sum0 += __shfl_xor_sync(0xffffffffu, sum0, 1);
        sum0 += __shfl_xor_sync(0xffffffffu, sum0, 2);
        sum1 += __shfl_xor_sync(0xffffffffu, sum1, 1);
        sum1 += __shfl_xor_sync(0xffffffffu, sum1, 2);
        if (t == 0) {
            psum[wn * 64 + r0]     = sum0;
            psum[wn * 64 + r0 + 8] = sum1;
        }

#pragma unroll
        for (int nt = 0; nt < 8; nt++) {
            oc[nt][0] *= corr0; oc[nt][1] *= corr0;
            oc[nt][2] *= corr1; oc[nt][3] *= corr1;
        }
        __syncthreads();
        if (wn == 0 && t == 0) {
            mrow[r0] = mnew0;
            mrow[r0 + 8] = mnew1;
            lrow[r0]     = lrow[r0] * corr0 + psum[r0] + psum[64 + r0];
            lrow[r0 + 8] = lrow[r0 + 8] * corr1 + psum[r0 + 8] + psum[64 + r0 + 8];
        }

#pragma unroll
        for (int kk = 0; kk < 8; kk++) {
            uint32_t ph[4], pl[4];
            ldsm_x4(ph, smb + phoff + kk * 32);
            ldsm_x4(pl, smb + ploff + kk * 32);
            const int c = kk * 8 + t;
#pragma unroll
            for (int nt = 0; nt < 8; nt++) {
                const int vc = wn * 64 + nt * 8 + g;
                uint32_t vh[2], vl[2];
                vh[0] = __float_as_uint(Vhi[(c) * FSTR_V + vc]);
                vh[1] = __float_as_uint(Vhi[(c + 4) * FSTR_V + vc]);
                vl[0] = __float_as_uint(Vlo[(c) * FSTR_V + vc]);
                vl[1] = __float_as_uint(Vlo[(c + 4) * FSTR_V + vc]);
                mma_tf32(oc[nt], ph, vh);
                mma_tf32(oc[nt], pl, vh);
                mma_tf32(oc[nt], ph, vl);
            }
        }
    }

    __syncthreads();
    float linv0 = 1.f / lrow[r0];
    float linv1 = 1.f / lrow[r0 + 8];
    float* Og = g_O + ((long)(b * TSEQ + q0)) * DIMC + h * DH;
#pragma unroll
    for (int nt = 0; nt < 8; nt++) {
        int c = wn * 64 + nt * 8 + 2 * t;
        *(float2*)&Og[(long)r0 * DIMC + c] = make_float2(
            __uint_as_float(cvt_tf32(oc[nt][0] * linv0)),
            __uint_as_float(cvt_tf32(oc[nt][1] * linv0)));
        *(float2*)&Og[(long)(r0 + 8) * DIMC + c] = make_float2(
            __uint_as_float(cvt_tf32(oc[nt][2] * linv1)),
            __uint_as_float(cvt_tf32(oc[nt][3] * linv1)));
    }
}

// =====================================================================
// launch
// =====================================================================
extern "C" void kernel_launch(void* const* d_in, const int* in_sizes, int n_in,
                              void* d_out, int out_size) {
    const float* X  = (const float*)d_in[0];
    const float* Wq = (const float*)d_in[1];
    const float* Wk = (const float*)d_in[2];
    const float* Wv = (const float*)d_in[3];
    const float* Wo = (const float*)d_in[4];
    float* out = (float*)d_out;

    float *Qp, *Kp, *Vp, *Op, *Xt, *Wqt, *Wkt, *Wvt, *Wot;
    cudaGetSymbolAddress((void**)&Qp, g_Q);
    cudaGetSymbolAddress((void**)&Kp, g_K);
    cudaGetSymbolAddress((void**)&Vp, g_V);
    cudaGetSymbolAddress((void**)&Op, g_O);
    cudaGetSymbolAddress((void**)&Xt, g_Xt);
    cudaGetSymbolAddress((void**)&Wqt, g_Wqt);
    cudaGetSymbolAddress((void**)&Wkt, g_Wkt);
    cudaGetSymbolAddress((void**)&Wvt, g_Wvt);
    cudaGetSymbolAddress((void**)&Wot, g_Wot);

    cudaFuncSetAttribute(gemm_tf32, cudaFuncAttributeMaxDynamicSharedMemorySize,
                         GEMM_SMEM_BYTES);
    cudaFuncSetAttribute(flash_tc, cudaFuncAttributeMaxDynamicSharedMemorySize,
                         FLASH_TC_BYTES);

    rope_table<<<(TSEQ * 64 + 255) / 256, 256>>>();

    {
        int n4x = (BT * DIMC) / 4;
        cvt_buf<<<(n4x + 255) / 256, 256>>>(X, Xt, n4x);
        int n4q = (DIMC * DIMC) / 4;
        cvt_buf<<<(n4q + 255) / 256, 256>>>(Wq, Wqt, n4q);
        int n4k = (DIMC * KVDIM) / 4;
        cvt_buf<<<(n4k + 255) / 256, 256>>>(Wk, Wkt, n4k);
        cvt_buf<<<(n4k + 255) / 256, 256>>>(Wv, Wvt, n4k);
        cvt_buf<<<(n4q + 255) / 256, 256>>>(Wo, Wot, n4q);
    }

    gemm_tf32<<<dim3(DIMC / 128, BT / 128), 256, GEMM_SMEM_BYTES>>>(Xt, Wqt, Qp, BT, DIMC, DIMC);
    gemm_tf32<<<dim3(KVDIM / 128, BT / 128), 256, GEMM_SMEM_BYTES>>>(Xt, Wkt, Kp, BT, KVDIM, DIMC);
    gemm_tf32<<<dim3(KVDIM / 128, BT / 128), 256, GEMM_SMEM_BYTES>>>(Xt, Wvt, Vp, BT, KVDIM, DIMC);

    {
        int totq = BT * NH * 64;
        rope_apply<<<(totq + 255) / 256, 256>>>(Qp, NH, totq);
        int totk = BT * NKV * 64;
        rope_apply<<<(totk + 255) / 256, 256>>>(Kp, NKV, totk);
    }

    flash_tc<<<dim3(TSEQ / 64, BB * NH), 256, FLASH_TC_BYTES>>>();

    gemm_tf32<<<dim3(DIMC / 128, BT / 128), 256, GEMM_SMEM_BYTES>>>(Op, Wot, out, BT, DIMC, DIMC);
}

// round 9
// speedup vs baseline: 1.5629x; 1.3326x over previous
#include <cuda_runtime.h>
#include <cuda_fp16.h>
#include <math.h>
#include <stdint.h>

#define DIMC   4096
#define NH     32
#define NKV    8
#define DH     128
#define BB     2
#define TSEQ   2048
#define BT     (BB * TSEQ)
#define QKVN   6144          // fused Q|K|V output width
#define KOFF   4096
#define VOFF   5120

// ---- scratch ----
__device__ float  g_QKV[BT * QKVN];      // fused projection output (fp32)
__device__ __half g_Xh [BT * DIMC];
__device__ __half g_Wh [DIMC * QKVN];    // packed Wq|Wk|Wv (fp16)
__device__ __half g_Woh[DIMC * DIMC];
__device__ __half g_Oh [BT * DIMC];      // attention output (fp16)
__device__ float  g_cos[TSEQ * 64];
__device__ float  g_sin[TSEQ * 64];

// ---------------- helpers ----------------
__device__ __forceinline__ uint32_t cvt_tf32(float f) {
    uint32_t u;
    asm("cvt.rna.tf32.f32 %0, %1;" : "=r"(u) : "f"(f));
    return u;
}
__device__ __forceinline__ void split_tf32(float x, uint32_t& hi, uint32_t& lo) {
    hi = cvt_tf32(x);
    lo = cvt_tf32(x - __uint_as_float(hi));
}
__device__ __forceinline__ void mma_tf32(float* c, const uint32_t* a, const uint32_t* b) {
    asm volatile(
        "mma.sync.aligned.m16n8k8.row.col.f32.tf32.tf32.f32 "
        "{%0,%1,%2,%3}, {%4,%5,%6,%7}, {%8,%9}, {%0,%1,%2,%3};"
        : "+f"(c[0]), "+f"(c[1]), "+f"(c[2]), "+f"(c[3])
        : "r"(a[0]), "r"(a[1]), "r"(a[2]), "r"(a[3]), "r"(b[0]), "r"(b[1]));
}
__device__ __forceinline__ void mma_f16(float* c, const uint32_t* a, const uint32_t* b) {
    asm volatile(
        "mma.sync.aligned.m16n8k16.row.col.f32.f16.f16.f32 "
        "{%0,%1,%2,%3}, {%4,%5,%6,%7}, {%8,%9}, {%0,%1,%2,%3};"
        : "+f"(c[0]), "+f"(c[1]), "+f"(c[2]), "+f"(c[3])
        : "r"(a[0]), "r"(a[1]), "r"(a[2]), "r"(a[3]), "r"(b[0]), "r"(b[1]));
}
__device__ __forceinline__ void cpasync16(uint32_t dst, const void* src) {
    asm volatile("cp.async.cg.shared.global [%0], [%1], 16;" :: "r"(dst), "l"(src));
}
__device__ __forceinline__ void ldsm_x4(uint32_t* r, uint32_t addr) {
    asm volatile("ldmatrix.sync.aligned.m8n8.x4.shared.b16 {%0,%1,%2,%3}, [%4];"
                 : "=r"(r[0]), "=r"(r[1]), "=r"(r[2]), "=r"(r[3]) : "r"(addr));
}
__device__ __forceinline__ void ldsm_x4_t(uint32_t* r, uint32_t addr) {
    asm volatile("ldmatrix.sync.aligned.m8n8.x4.trans.shared.b16 {%0,%1,%2,%3}, [%4];"
                 : "=r"(r[0]), "=r"(r[1]), "=r"(r[2]), "=r"(r[3]) : "r"(addr));
}

// pack fp32 matrix [rows x w] into fp16 dst at column offset coff, row stride dstr
__global__ void pack_w(const float* __restrict__ src, __half* __restrict__ dst,
                       int w, int coff, int dstr, int n4) {
    int i = blockIdx.x * 256 + threadIdx.x;
    if (i >= n4) return;
    int idx = i * 4;
    int r = idx / w, c = idx % w;
    float4 v = *(const float4*)(src + idx);
    __half2* p = (__half2*)(dst + (long)r * dstr + coff + c);
    p[0] = __floats2half2_rn(v.x, v.y);
    p[1] = __floats2half2_rn(v.z, v.w);
}

// =====================================================================
// FP16 GEMM: C[M,N](f32) = A[M,K](f16) @ B[K,N](f16).
// 128x128 CTA tile, BK=32, 256 threads, warp tile 64x32, m16n8k16.
// cp.async double buffer; ldmatrix A (x4) + B (x4.trans).
// =====================================================================
#define GBK  32
#define ASTR 40     // halves; 80B row stride -> conflict-free ldsm phases
#define BSTR 136    // halves; 272B row stride -> conflict-free ldsm.trans
#define GEMM_SMEM_BYTES ((2 * 128 * ASTR + 2 * GBK * BSTR) * 2)

__global__ __launch_bounds__(256) void gemm_f16(const __half* __restrict__ A,
                                                const __half* __restrict__ B,
                                                float* __restrict__ C,
                                                int M, int N, int K) {
    extern __shared__ __half hsm[];
    __half* As = hsm;                      // [2][128][ASTR]
    __half* Bs = hsm + 2 * 128 * ASTR;     // [2][GBK][BSTR]

    const int tid  = threadIdx.x;
    const int brow = blockIdx.y * 128;
    const int bcol = blockIdx.x * 128;
    const int wid  = tid >> 5, lane = tid & 31;
    const int g    = lane >> 2, t = lane & 3;
    const int m_base = (wid & 1) * 64;
    const int n_base = (wid >> 1) * 32;

    // loader coords (16B = 8 halves per cp.async)
    const int a_r = tid >> 2;              // +64*i  (128 rows, 4 chunks/row)
    const int a_c = (tid & 3) * 8;
    const int b_r = tid >> 4;              // +16*i  (32 rows, 16 chunks/row)
    const int b_c = (tid & 15) * 8;

    // ldmatrix lane mapping
    const int xr8 = (lane & 7) + ((lane >> 3) & 1) * 8;
    const int xc8 = (lane >> 4) * 8;
    const uint32_t sAb = (uint32_t)__cvta_generic_to_shared(As);
    const uint32_t sBb = (uint32_t)__cvta_generic_to_shared(Bs);
    uint32_t aoff[4];
#pragma unroll
    for (int mi = 0; mi < 4; mi++)
        aoff[mi] = ((m_base + 16 * mi + xr8) * ASTR + xc8) * 2;
    uint32_t boff[2];
#pragma unroll
    for (int nj = 0; nj < 2; nj++)
        boff[nj] = (xr8 * BSTR + n_base + nj * 16 + xc8) * 2;

    float c[4][4][4];
#pragma unroll
    for (int mi = 0; mi < 4; mi++)
#pragma unroll
        for (int ni = 0; ni < 4; ni++)
#pragma unroll
            for (int r = 0; r < 4; r++) c[mi][ni][r] = 0.f;

    const int KT = K / GBK;
    {
#pragma unroll
        for (int i = 0; i < 2; i++) {
            int r = a_r + 64 * i;
            cpasync16((uint32_t)__cvta_generic_to_shared(&As[r * ASTR + a_c]),
                      A + (long)(brow + r) * K + a_c);
        }
#pragma unroll
        for (int i = 0; i < 2; i++) {
            int r = b_r + 16 * i;
            cpasync16((uint32_t)__cvta_generic_to_shared(&Bs[r * BSTR + b_c]),
                      B + (long)r * N + bcol + b_c);
        }
        asm volatile("cp.async.commit_group;");
    }

    int s = 0;
    for (int kt = 0; kt < KT; kt++) {
        if (kt + 1 < KT) {
            const int k0 = (kt + 1) * GBK;
            __half* as = As + (s ^ 1) * 128 * ASTR;
            __half* bs = Bs + (s ^ 1) * GBK * BSTR;
#pragma unroll
            for (int i = 0; i < 2; i++) {
                int r = a_r + 64 * i;
                cpasync16((uint32_t)__cvta_generic_to_shared(&as[r * ASTR + a_c]),
                          A + (long)(brow + r) * K + k0 + a_c);
            }
#pragma unroll
            for (int i = 0; i < 2; i++) {
                int r = b_r + 16 * i;
                cpasync16((uint32_t)__cvta_generic_to_shared(&bs[r * BSTR + b_c]),
                          B + (long)(k0 + r) * N + bcol + b_c);
            }
            asm volatile("cp.async.commit_group;");
            asm volatile("cp.async.wait_group 1;");
        } else {
            asm volatile("cp.async.wait_group 0;");
        }
        __syncthreads();

        const uint32_t ab = sAb + (uint32_t)(s * 128 * ASTR * 2);
        const uint32_t bb = sBb + (uint32_t)(s * GBK * BSTR * 2);
#pragma unroll
        for (int j = 0; j < 2; j++) {                 // two k16 steps
            uint32_t af[4][4], bq[2][4];
#pragma unroll
            for (int mi = 0; mi < 4; mi++)
                ldsm_x4(af[mi], ab + aoff[mi] + j * 32);          // +16 halves
#pragma unroll
            for (int nj = 0; nj < 2; nj++)
                ldsm_x4_t(bq[nj], bb + boff[nj] + j * 16 * BSTR * 2);
#pragma unroll
            for (int mi = 0; mi < 4; mi++)
#pragma unroll
                for (int nj = 0; nj < 2; nj++) {
                    mma_f16(c[mi][2 * nj + 0], af[mi], &bq[nj][0]);
                    mma_f16(c[mi][2 * nj + 1], af[mi], &bq[nj][2]);
                }
        }
        __syncthreads();
        s ^= 1;
    }

#pragma unroll
    for (int mi = 0; mi < 4; mi++) {
#pragma unroll
        for (int ni = 0; ni < 4; ni++) {
            long row = brow + m_base + 16 * mi + g;
            int  col = bcol + n_base + 8 * ni + 2 * t;
            *(float2*)&C[row * N + col]       = make_float2(c[mi][ni][0], c[mi][ni][1]);
            *(float2*)&C[(row + 8) * N + col] = make_float2(c[mi][ni][2], c[mi][ni][3]);
        }
    }
}

// =====================================================================
// RoPE
// =====================================================================
__global__ void rope_table() {
    int idx = blockIdx.x * 256 + threadIdx.x;
    if (idx >= TSEQ * 64) return;
    int d = idx & 63, t = idx >> 6;
    double inv = pow(10000.0, -(double)d / 64.0);
    double ang = (double)t * inv;
    g_cos[idx] = (float)cos(ang);
    g_sin[idx] = (float)sin(ang);
}

// x rows = [bt][stride]; heads at hoff + h*128
__global__ void rope_apply2(float* __restrict__ x, int nheads, int stride, int hoff, int total) {
    int idx = blockIdx.x * 256 + threadIdx.x;
    if (idx >= total) return;
    int d  = idx & 63;
    int r  = idx >> 6;                 // bt*nheads + h
    int h  = r % nheads;
    int bt = r / nheads;
    int t  = bt % TSEQ;
    long base = (long)bt * stride + hoff + h * 128 + d;
    float c = g_cos[t * 64 + d], s = g_sin[t * 64 + d];
    float x1 = x[base], x2 = x[base + 64];
    x[base]      = x1 * c - x2 * s;
    x[base + 64] = x1 * s + x2 * c;
}

// =====================================================================
// Tensor-core flash attention, 3xTF32 (internals unchanged from R8).
// Reads fused QKV (f32, stride 6144); writes O as fp16.
// =====================================================================
#define FSTR_QK 132
#define FSTR_V  136
#define FSTR_P  68

#define KHI_OFF  0
#define KLO_OFF  (KHI_OFF + 64 * FSTR_QK)
#define VHI_OFF  (KLO_OFF + 64 * FSTR_QK)
#define VLO_OFF  (VHI_OFF + 64 * FSTR_V)
#define PHI_OFF  (VLO_OFF + 64 * FSTR_V)
#define PLO_OFF  (PHI_OFF + 64 * FSTR_P)
#define MROW_OFF (PLO_OFF + 64 * FSTR_P)
#define LROW_OFF (MROW_OFF + 64)
#define PMAX_OFF (LROW_OFF + 64)
#define PSUM_OFF (PMAX_OFF + 128)
#define FLASH_TC_FLOATS (PSUM_OFF + 128)
#define FLASH_TC_BYTES  (FLASH_TC_FLOATS * 4)

__global__ __launch_bounds__(256, 1) void flash_tc() {
    extern __shared__ float sm[];
    float* Khi  = sm + KHI_OFF;
    float* Klo  = sm + KLO_OFF;
    float* Vhi  = sm + VHI_OFF;
    float* Vlo  = sm + VLO_OFF;
    float* Phi  = sm + PHI_OFF;
    float* Plo  = sm + PLO_OFF;
    float* mrow = sm + MROW_OFF;
    float* lrow = sm + LROW_OFF;
    float* pmax = sm + PMAX_OFF;
    float* psum = sm + PSUM_OFF;

    const int tid = threadIdx.x;
    const int qt  = blockIdx.x;
    const int bh  = blockIdx.y;
    const int b   = bh >> 5;
    const int h   = bh & 31;
    const int kvh = h >> 2;
    const int q0  = qt * 64;
    const int lane = tid & 31, wid = tid >> 5;
    const int g = lane >> 2, t = lane & 3;
    const int wm = wid & 3, wn = wid >> 2;
    const int r0 = wm * 16 + g;

    const int xr = lane & 15;
    const int xc = (lane >> 4) << 2;
    const uint32_t smb = (uint32_t)__cvta_generic_to_shared(sm);
    uint32_t khoff[2], kloff[2];
#pragma unroll
    for (int j = 0; j < 2; j++) {
        khoff[j] = (KHI_OFF + (wn * 32 + 16 * j + xr) * FSTR_QK + xc) * 4;
        kloff[j] = (KLO_OFF + (wn * 32 + 16 * j + xr) * FSTR_QK + xc) * 4;
    }
    const uint32_t phoff = (PHI_OFF + (wm * 16 + xr) * FSTR_P + xc) * 4;
    const uint32_t ploff = (PLO_OFF + (wm * 16 + xr) * FSTR_P + xc) * 4;

    // stage Q tile into Khi temp
    const float* Qg = g_QKV + ((long)(b * TSEQ + q0)) * QKVN + h * DH;
#pragma unroll
    for (int it = 0; it < 8; it++) {
        int idx = it * 256 + tid;
        int row = idx >> 5, c4 = (idx & 31) << 2;
        *(float4*)&Khi[row * FSTR_QK + c4] = *(const float4*)&Qg[(long)row * QKVN + c4];
    }
    if (tid < 64) { mrow[tid] = -1e30f; lrow[tid] = 0.f; }
    __syncthreads();

    const float scale = 0.0883883476483184f;
    uint32_t qhi[16][4];
    uint32_t qlo[16][4];
#pragma unroll
    for (int kk = 0; kk < 16; kk++) {
        const int c = kk * 8 + t;
        float v0 = Khi[r0 * FSTR_QK + c] * scale;
        float v1 = Khi[(r0 + 8) * FSTR_QK + c] * scale;
        float v2 = Khi[r0 * FSTR_QK + c + 4] * scale;
        float v3 = Khi[(r0 + 8) * FSTR_QK + c + 4] * scale;
        split_tf32(v0, qhi[kk][0], qlo[kk][0]);
        split_tf32(v1, qhi[kk][1], qlo[kk][1]);
        split_tf32(v2, qhi[kk][2], qlo[kk][2]);
        split_tf32(v3, qhi[kk][3], qlo[kk][3]);
    }

    float oc[8][4];
#pragma unroll
    for (int nt = 0; nt < 8; nt++)
#pragma unroll
        for (int r = 0; r < 4; r++) oc[nt][r] = 0.f;

    for (int kt = 0; kt <= qt; kt++) {
        const int k0 = kt * 64;
        const float* Kg = g_QKV + ((long)(b * TSEQ + k0)) * QKVN + KOFF + kvh * DH;
        const float* Vg = g_QKV + ((long)(b * TSEQ + k0)) * QKVN + VOFF + kvh * DH;

        __syncthreads();
#pragma unroll
        for (int it = 0; it < 8; it++) {
            int idx = it * 256 + tid;
            int row = idx >> 5, c4 = (idx & 31) << 2;
            float4 kq = *(const float4*)&Kg[(long)row * QKVN + c4];
            float4 vq = *(const float4*)&Vg[(long)row * QKVN + c4];
            uint32_t h0, h1, h2, h3, l0, l1, l2, l3;
            split_tf32(kq.x, h0, l0); split_tf32(kq.y, h1, l1);
            split_tf32(kq.z, h2, l2); split_tf32(kq.w, h3, l3);
            *(float4*)&Khi[row * FSTR_QK + c4] = make_float4(
                __uint_as_float(h0), __uint_as_float(h1), __uint_as_float(h2), __uint_as_float(h3));
            *(float4*)&Klo[row * FSTR_QK + c4] = make_float4(
                __uint_as_float(l0), __uint_as_float(l1), __uint_as_float(l2), __uint_as_float(l3));
            split_tf32(vq.x, h0, l0); split_tf32(vq.y, h1, l1);
            split_tf32(vq.z, h2, l2); split_tf32(vq.w, h3, l3);
            *(float4*)&Vhi[row * FSTR_V + c4] = make_float4(
                __uint_as_float(h0), __uint_as_float(h1), __uint_as_float(h2), __uint_as_float(h3));
            *(float4*)&Vlo[row * FSTR_V + c4] = make_float4(
                __uint_as_float(l0), __uint_as_float(l1), __uint_as_float(l2), __uint_as_float(l3));
        }
        __syncthreads();

        float sc[4][4];
#pragma unroll
        for (int nt = 0; nt < 4; nt++)
#pragma unroll
            for (int r = 0; r < 4; r++) sc[nt][r] = 0.f;

#pragma unroll
        for (int kk = 0; kk < 16; kk++) {
            uint32_t bh4[2][4], bl4[2][4];
#pragma unroll
            for (int j = 0; j < 2; j++) {
                ldsm_x4(bh4[j], smb + khoff[j] + kk * 32);
                ldsm_x4(bl4[j], smb + kloff[j] + kk * 32);
            }
#pragma unroll
            for (int j = 0; j < 2; j++) {
#pragma unroll
                for (int hh = 0; hh < 2; hh++) {
                    const int nt = 2 * j + hh;
                    uint32_t bhf[2] = { bh4[j][hh], bh4[j][2 + hh] };
                    uint32_t blf[2] = { bl4[j][hh], bl4[j][2 + hh] };
                    mma_tf32(sc[nt], qhi[kk], bhf);
                    mma_tf32(sc[nt], qlo[kk], bhf);
                    mma_tf32(sc[nt], qhi[kk], blf);
                }
            }
        }

        if (kt == qt) {
#pragma unroll
            for (int nt = 0; nt < 4; nt++) {
                int c = wn * 32 + nt * 8 + 2 * t;
                if (c     > r0)     sc[nt][0] = -1e30f;
                if (c + 1 > r0)     sc[nt][1] = -1e30f;
                if (c     > r0 + 8) sc[nt][2] = -1e30f;
                if (c + 1 > r0 + 8) sc[nt][3] = -1e30f;
            }
        }

        float mx0 = -1e30f, mx1 = -1e30f;
#pragma unroll
        for (int nt = 0; nt < 4; nt++) {
            mx0 = fmaxf(mx0, fmaxf(sc[nt][0], sc[nt][1]));
            mx1 = fmaxf(mx1, fmaxf(sc[nt][2], sc[nt][3]));
        }
        mx0 = fmaxf(mx0, __shfl_xor_sync(0xffffffffu, mx0, 1));
        mx0 = fmaxf(mx0, __shfl_xor_sync(0xffffffffu, mx0, 2));
        mx1 = fmaxf(mx1, __shfl_xor_sync(0xffffffffu, mx1, 1));
        mx1 = fmaxf(mx1, __shfl_xor_sync(0xffffffffu, mx1, 2));
        if (t == 0) {
            pmax[wn * 64 + r0]     = mx0;
            pmax[wn * 64 + r0 + 8] = mx1;
        }
        __syncthreads();
        float mold0 = mrow[r0], mold1 = mrow[r0 + 8];
        float mnew0 = fmaxf(mold0, fmaxf(pmax[r0], pmax[64 + r0]));
        float mnew1 = fmaxf(mold1, fmaxf(pmax[r0 + 8], pmax[64 + r0 + 8]));
        float corr0 = __expf(mold0 - mnew0);
        float corr1 = __expf(mold1 - mnew1);

        float sum0 = 0.f, sum1 = 0.f;
#pragma unroll
        for (int nt = 0; nt < 4; nt++) {
            float p00 = __expf(sc[nt][0] - mnew0);
            float p01 = __expf(sc[nt][1] - mnew0);
            float p10 = __expf(sc[nt][2] - mnew1);
            float p11 = __expf(sc[nt][3] - mnew1);
            sum0 += p00 + p01;
            sum1 += p10 + p11;
            uint32_t h00, h01, h10, h11, l00, l01, l10, l11;
            split_tf32(p00, h00, l00); split_tf32(p01, h01, l01);
            split_tf32(p10, h10, l10); split_tf32(p11, h11, l11);
            int c = wn * 32 + nt * 8 + 2 * t;
            *(float2*)&Phi[r0 * FSTR_P + c] =
                make_float2(__uint_as_float(h00), __uint_as_float(h01));
            *(float2*)&Plo[r0 * FSTR_P + c] =
                make_float2(__uint_as_float(l00), __uint_as_float(l01));
            *(float2*)&Phi[(r0 + 8) * FSTR_P + c] =
                make_float2(__uint_as_float(h10), __uint_as_float(h11));
            *(float2*)&Plo[(r0 + 8) * FSTR_P + c] =
                make_float2(__uint_as_float(l10), __uint_as_float(l11));
        }
        sum0 += __shfl_xor_sync(0xffffffffu, sum0, 1);
        sum0 += __shfl_xor_sync(0xffffffffu, sum0, 2);
        sum1 += __shfl_xor_sync(0xffffffffu, sum1, 1);
        sum1 += __shfl_xor_sync(0xffffffffu, sum1, 2);
        if (t == 0) {
            psum[wn * 64 + r0]     = sum0;
            psum[wn * 64 + r0 + 8] = sum1;
        }

#pragma unroll
        for (int nt = 0; nt < 8; nt++) {
            oc[nt][0] *= corr0; oc[nt][1] *= corr0;
            oc[nt][2] *= corr1; oc[nt][3] *= corr1;
        }
        __syncthreads();
        if (wn == 0 && t == 0) {
            mrow[r0] = mnew0;
            mrow[r0 + 8] = mnew1;
            lrow[r0]     = lrow[r0] * corr0 + psum[r0] + psum[64 + r0];
            lrow[r0 + 8] = lrow[r0 + 8] * corr1 + psum[r0 + 8] + psum[64 + r0 + 8];
        }

#pragma unroll
        for (int kk = 0; kk < 8; kk++) {
            uint32_t ph[4], pl[4];
            ldsm_x4(ph, smb + phoff + kk * 32);
            ldsm_x4(pl, smb + ploff + kk * 32);
            const int c = kk * 8 + t;
#pragma unroll
            for (int nt = 0; nt < 8; nt++) {
                const int vc = wn * 64 + nt * 8 + g;
                uint32_t vh[2], vl[2];
                vh[0] = __float_as_uint(Vhi[(c) * FSTR_V + vc]);
                vh[1] = __float_as_uint(Vhi[(c + 4) * FSTR_V + vc]);
                vl[0] = __float_as_uint(Vlo[(c) * FSTR_V + vc]);
                vl[1] = __float_as_uint(Vlo[(c + 4) * FSTR_V + vc]);
                mma_tf32(oc[nt], ph, vh);
                mma_tf32(oc[nt], pl, vh);
                mma_tf32(oc[nt], ph, vl);
            }
        }
    }

    __syncthreads();
    float linv0 = 1.f / lrow[r0];
    float linv1 = 1.f / lrow[r0 + 8];
    __half* Og = g_Oh + ((long)(b * TSEQ + q0)) * DIMC + h * DH;
#pragma unroll
    for (int nt = 0; nt < 8; nt++) {
        int c = wn * 64 + nt * 8 + 2 * t;
        *(__half2*)&Og[(long)r0 * DIMC + c] =
            __floats2half2_rn(oc[nt][0] * linv0, oc[nt][1] * linv0);
        *(__half2*)&Og[(long)(r0 + 8) * DIMC + c] =
            __floats2half2_rn(oc[nt][2] * linv1, oc[nt][3] * linv1);
    }
}

// =====================================================================
// launch
// =====================================================================
extern "C" void kernel_launch(void* const* d_in, const int* in_sizes, int n_in,
                              void* d_out, int out_size) {
    const float* X  = (const float*)d_in[0];
    const float* Wq = (const float*)d_in[1];
    const float* Wk = (const float*)d_in[2];
    const float* Wv = (const float*)d_in[3];
    const float* Wo = (const float*)d_in[4];
    float* out = (float*)d_out;

    float  *QKVp;
    __half *Xh, *Wh, *Woh, *Oh;
    cudaGetSymbolAddress((void**)&QKVp, g_QKV);
    cudaGetSymbolAddress((void**)&Xh,  g_Xh);
    cudaGetSymbolAddress((void**)&Wh,  g_Wh);
    cudaGetSymbolAddress((void**)&Woh, g_Woh);
    cudaGetSymbolAddress((void**)&Oh,  g_Oh);

    cudaFuncSetAttribute(gemm_f16, cudaFuncAttributeMaxDynamicSharedMemorySize,
                         GEMM_SMEM_BYTES);
    cudaFuncSetAttribute(flash_tc, cudaFuncAttributeMaxDynamicSharedMemorySize,
                         FLASH_TC_BYTES);

    rope_table<<<(TSEQ * 64 + 255) / 256, 256>>>();

    // fp16 conversions / packing
    {
        int n4x = (BT * DIMC) / 4;
        pack_w<<<(n4x + 255) / 256, 256>>>(X, Xh, DIMC, 0, DIMC, n4x);
        int n4q = (DIMC * DIMC) / 4;
        pack_w<<<(n4q + 255) / 256, 256>>>(Wq, Wh, DIMC, 0, QKVN, n4q);
        int n4k = (DIMC * 1024) / 4;
        pack_w<<<(n4k + 255) / 256, 256>>>(Wk, Wh, 1024, KOFF, QKVN, n4k);
        pack_w<<<(n4k + 255) / 256, 256>>>(Wv, Wh, 1024, VOFF, QKVN, n4k);
        pack_w<<<(n4q + 255) / 256, 256>>>(Wo, Woh, DIMC, 0, DIMC, n4q);
    }

    // fused QKV projection
    gemm_f16<<<dim3(QKVN / 128, BT / 128), 256, GEMM_SMEM_BYTES>>>(Xh, Wh, QKVp, BT, QKVN, DIMC);

    // RoPE on Q and K (inside fused buffer)
    {
        int totq = BT * NH * 64;
        rope_apply2<<<(totq + 255) / 256, 256>>>(QKVp, NH, QKVN, 0, totq);
        int totk = BT * NKV * 64;
        rope_apply2<<<(totk + 255) / 256, 256>>>(QKVp, NKV, QKVN, KOFF, totk);
    }

    flash_tc<<<dim3(TSEQ / 64, BB * NH), 256, FLASH_TC_BYTES>>>();

    // output projection
    gemm_f16<<<dim3(DIMC / 128, BT / 128), 256, GEMM_SMEM_BYTES>>>(Oh, Woh, out, BT, DIMC, DIMC);
}